// round 11
// baseline (speedup 1.0000x reference)
#include <cuda_runtime.h>
#include <cuda_bf16.h>
#include <math.h>
#include <stdint.h>

#define NB 2
#define NS 1024
#define ND 128
#define ND2 256
#define NN 256
#define NH 2
#define NL 2
#define NLH (NL*NH)
#define NV 32000
#define PHI_F 1.6180339887498949f

#define INST_Q   (NB*NS*ND2)
#define INST_SC  ((size_t)NB*NS*NS)
#define INST_RET (NB*NS*ND2)
#define LAY_X    (NB*NS*ND)

// ---------------- scratch ----------------
static __device__ float g_wemb[NB*NS*ND];
static __device__ float g_bemb[NB*NS*ND];
static __device__ float g_sr  [NB*NS*ND];
static __device__ float g_si  [NB*NS*ND];
static __device__ float g_K   [NB*NS*ND2];
static __device__ float g_x   [NB*NS*ND];
static __device__ float g_Q   [NLH*INST_Q];
static __device__ float g_sc  [NLH*NB*NS*NS];
static __device__ float g_ret [NLH*INST_RET];
static __device__ float g_echo[NL*LAY_X];
static __device__ float g_cs  [NB*NS*NN];
static __device__ float g_ss  [NB*NS*NN];
static __device__ float g_rwT[NL*ND*NN];
static __device__ float g_bT [NL*ND*NN];
static __device__ float g_acT[NL*ND*NN];
static __device__ float g_asT[NL*ND*NN];
// bf16 hi/lo splits for logits GEMM
static __device__ __nv_bfloat16 g_oph[NV*ND];
static __device__ __nv_bfloat16 g_opl[NV*ND];
static __device__ __nv_bfloat16 g_xh [NB*NS*ND];
static __device__ __nv_bfloat16 g_xl [NB*NS*ND];

__device__ __forceinline__ float to_tf32(float v) {
    float r; asm("cvt.rna.tf32.f32 %0, %1;" : "=f"(r) : "f"(v)); return r;
}
__device__ __forceinline__ void mma_tf32(float* c, const uint32_t* a, const uint32_t* b) {
    asm volatile(
        "mma.sync.aligned.m16n8k8.row.col.f32.tf32.tf32.f32 "
        "{%0,%1,%2,%3},{%4,%5,%6,%7},{%8,%9},{%0,%1,%2,%3};"
        : "+f"(c[0]), "+f"(c[1]), "+f"(c[2]), "+f"(c[3])
        : "r"(a[0]), "r"(a[1]), "r"(a[2]), "r"(a[3]), "r"(b[0]), "r"(b[1]));
}
__device__ __forceinline__ void mma_bf16(float* c, const uint32_t* a, const uint32_t* b) {
    asm volatile(
        "mma.sync.aligned.m16n8k16.row.col.f32.bf16.bf16.f32 "
        "{%0,%1,%2,%3},{%4,%5,%6,%7},{%8,%9},{%0,%1,%2,%3};"
        : "+f"(c[0]), "+f"(c[1]), "+f"(c[2]), "+f"(c[3])
        : "r"(a[0]), "r"(a[1]), "r"(a[2]), "r"(a[3]), "r"(b[0]), "r"(b[1]));
}
__device__ __forceinline__ uint32_t smem_u32(const void* p) {
    uint32_t a;
    asm("{ .reg .u64 t; cvta.to.shared.u64 t, %1; cvt.u32.u64 %0, t; }" : "=r"(a) : "l"(p));
    return a;
}
#define LDSM_X4(r0, r1, r2, r3, addr) \
    asm volatile("ldmatrix.sync.aligned.m8n8.x4.shared.b16 {%0,%1,%2,%3}, [%4];" \
                 : "=r"(r0), "=r"(r1), "=r"(r2), "=r"(r3) : "r"(addr))

// ---------------- 1. gather ----------------
__global__ void gather_kernel(const int* __restrict__ ids, const float* __restrict__ embed) {
    int i = blockIdx.x * blockDim.x + threadIdx.x;
    if (i >= NB*NS*ND) return;
    int d  = i % ND;
    int bs = i / ND;
    int tok = ids[bs];
    g_wemb[i] = embed[tok * ND2 + d];
    g_bemb[i] = embed[tok * ND2 + ND + d];
}

// ---------------- 2. euler scan, register-prefetched — numerics UNCHANGED ----------------
__global__ void scan_kernel() {
    int b = blockIdx.x;
    int d = threadIdx.x;
    float hr = 0.0f, hi = 0.0f;
    int base = b * NS * ND + d;
    float w  = g_wemb[base];
    float bb = g_bemb[base];
    for (int t = 0; t < NS; t++) {
        float wn = 0.0f, bn = 0.0f;
        if (t + 1 < NS) {
            wn = g_wemb[base + (t+1)*ND];
            bn = g_bemb[base + (t+1)*ND];
        }
        float wl = 1.0f + fabsf(w);
        float tphi = (float)t * PHI_F;
        float thr = hr / wl + bb + tphi;
        float thi = hi / wl + bb + tphi;
        float srv, crv, siv, civ;
        sincosf(thr, &srv, &crv);
        sincosf(thi, &siv, &civ);
        float nr = crv * civ - srv * siv;
        float ni = crv * siv + srv * civ;
        g_sr[base + t*ND] = nr;
        g_si[base + t*ND] = ni;
        g_x [base + t*ND] = nr + ni;
        int kb = (b*NS + t) * ND2;
        g_K[kb + d]      = nr;
        g_K[kb + ND + d] = ni;
        hr = nr; hi = ni;
        w = wn; bb = bn;
    }
}

// ---------------- weight prep ----------------
__global__ void ffnprep_kernel(const float* __restrict__ W, const float* __restrict__ Bp,
                               const float* __restrict__ ac, const float* __restrict__ as_) {
    int i = blockIdx.x * blockDim.x + threadIdx.x;
    if (i >= NL*NN*ND) return;
    int l = i / (NN*ND);
    int r = i % (NN*ND);
    int n = r / ND;
    int d = r % ND;
    int o = l*ND*NN + d*NN + n;
    g_rwT[o] = 1.0f / (1.0f + fabsf(W[i]));
    g_bT [o] = Bp[i];
    g_acT[o] = ac[i];
    g_asT[o] = as_[i];
}

__global__ void opsplit_kernel(const float* __restrict__ op) {
    int i = blockIdx.x * blockDim.x + threadIdx.x;
    if (i >= NV*ND) return;
    float v = op[i];
    __nv_bfloat16 h = __float2bfloat16(v);
    g_oph[i] = h;
    g_opl[i] = __float2bfloat16(v - __bfloat162float(h));
}

// ---------------- 3a. Q (MUFU cos; 1/16 scale folded in — exact pow2) ----------------
__global__ void q_kernel(const float* __restrict__ wq, const float* __restrict__ bq) {
    int i = blockIdx.x * blockDim.x + threadIdx.x;
    if (i >= NLH*NB*NS*ND) return;
    int inst = i / (NB*NS*ND);
    int j  = i % (NB*NS*ND);
    int d  = j % ND;
    int bs = j / ND;
    int t  = bs % NS;
    float wlq = 1.0f + fabsf(wq[inst*ND + d]);
    float bqv = bq[inst*ND + d];
    float tphi = (float)t * PHI_F;
    float thr = g_sr[j] / wlq + bqv + tphi;
    float thi = g_si[j] / wlq + bqv + tphi;
    float* Qb = g_Q + (size_t)inst*INST_Q;
    Qb[bs*ND2 + d]      = __cosf(thr) * 0.0625f;
    Qb[bs*ND2 + ND + d] = __cosf(thi) * 0.0625f;
}

// ---------------- 3b. scores via TF32 mma ----------------
#define KC 16
__global__ __launch_bounds__(256) void scores_mma_kernel() {
    int z = blockIdx.z;
    int b    = z % NB;
    int inst = z / NB;
    int q0 = blockIdx.x * 64;
    int k0 = blockIdx.y * 64;
    if (k0 > q0 + 63) return;
    const float* Qb = g_Q + (size_t)inst*INST_Q;
    float* scb = g_sc + (size_t)inst*INST_SC;
    __shared__ float Qs[64][KC+5];
    __shared__ float Ks[64][KC+5];
    int tid = threadIdx.x;
    int wid = tid >> 5, lane = tid & 31;
    int wm = wid >> 2, wn = wid & 3;
    int g  = lane >> 2, tg = lane & 3;
    float c[2][2][4];
    #pragma unroll
    for (int i = 0; i < 2; i++)
        #pragma unroll
        for (int j = 0; j < 2; j++)
            #pragma unroll
            for (int k = 0; k < 4; k++) c[i][j][k] = 0.0f;

    for (int kc = 0; kc < ND2; kc += KC) {
        for (int i = tid; i < 64*KC; i += 256) {
            int r = i >> 4, cc = i & 15;
            Qs[r][cc] = to_tf32(Qb[(b*NS + q0 + r)*ND2 + kc + cc]);
            Ks[r][cc] = to_tf32(g_K[(b*NS + k0 + r)*ND2 + kc + cc]);
        }
        __syncthreads();
        #pragma unroll
        for (int ks = 0; ks < KC; ks += 8) {
            uint32_t a[2][4], bf[2][2];
            #pragma unroll
            for (int mf = 0; mf < 2; mf++) {
                int br = wm*32 + mf*16;
                a[mf][0] = __float_as_uint(Qs[br + g    ][ks + tg    ]);
                a[mf][1] = __float_as_uint(Qs[br + g + 8][ks + tg    ]);
                a[mf][2] = __float_as_uint(Qs[br + g    ][ks + tg + 4]);
                a[mf][3] = __float_as_uint(Qs[br + g + 8][ks + tg + 4]);
            }
            #pragma unroll
            for (int nf = 0; nf < 2; nf++) {
                int bc = wn*16 + nf*8 + g;
                bf[nf][0] = __float_as_uint(Ks[bc][ks + tg    ]);
                bf[nf][1] = __float_as_uint(Ks[bc][ks + tg + 4]);
            }
            #pragma unroll
            for (int mf = 0; mf < 2; mf++)
                #pragma unroll
                for (int nf = 0; nf < 2; nf++)
                    mma_tf32(c[mf][nf], a[mf], bf[nf]);
        }
        __syncthreads();
    }
    #pragma unroll
    for (int mf = 0; mf < 2; mf++) {
        #pragma unroll
        for (int nf = 0; nf < 2; nf++) {
            int row = q0 + wm*32 + mf*16 + g;
            int col = k0 + wn*16 + nf*8 + 2*tg;
            size_t base0 = (size_t)(b*NS + row)*NS;
            size_t base1 = (size_t)(b*NS + row + 8)*NS;
            if (col     <= row)   scb[base0 + col]     = c[mf][nf][0];
            if (col + 1 <= row)   scb[base0 + col + 1] = c[mf][nf][1];
            if (col     <= row+8) scb[base1 + col]     = c[mf][nf][2];
            if (col + 1 <= row+8) scb[base1 + col + 1] = c[mf][nf][3];
        }
    }
}

// ---------------- 3c. single-pass softmax (scores bounded -> no max pass) ----------------
__global__ void softmax_kernel() {
    int q = blockIdx.x;
    int b = blockIdx.y;
    int inst = blockIdx.z;
    float* row = g_sc + (size_t)inst*INST_SC + (size_t)(b*NS + q)*NS;
    int tid = threadIdx.x;
    __shared__ float red[256];
    if (q == 0) {
        if (tid < 64) row[tid] = (tid == 0) ? 1.0f : 0.0f;
        return;
    }
    int len = q + 1;
    int kz_end = (q & ~63) + 64;
    float v[4];
    float sum = 0.0f;
    #pragma unroll
    for (int j = 0; j < 4; j++) {
        int k = tid + j*256;
        if (k < len) { v[j] = __expf(row[k]); sum += v[j]; }
        else v[j] = 0.0f;
    }
    red[tid] = sum; __syncthreads();
    for (int s = 128; s > 0; s >>= 1) { if (tid < s) red[tid] += red[tid+s]; __syncthreads(); }
    float inv = 1.0f / red[0];
    #pragma unroll
    for (int j = 0; j < 4; j++) {
        int k = tid + j*256;
        if (k < len)         row[k] = v[j] * inv;
        else if (k < kz_end) row[k] = 0.0f;
    }
}

// ---------------- 3d. retrieved = attn @ K via TF32 mma ----------------
__global__ __launch_bounds__(256) void av_mma_kernel() {
    int z = blockIdx.z;
    int b    = z % NB;
    int inst = z / NB;
    int q0 = blockIdx.x * 64;
    int n0 = blockIdx.y * 64;
    const float* scb = g_sc + (size_t)inst*INST_SC;
    float* retb = g_ret + (size_t)inst*INST_RET;
    __shared__ float As[64][KC+5];
    __shared__ float Bs[64][KC+5];
    int tid = threadIdx.x;
    int wid = tid >> 5, lane = tid & 31;
    int wm = wid >> 2, wn = wid & 3;
    int g  = lane >> 2, tg = lane & 3;
    float c[2][2][4];
    #pragma unroll
    for (int i = 0; i < 2; i++)
        #pragma unroll
        for (int j = 0; j < 2; j++)
            #pragma unroll
            for (int k = 0; k < 4; k++) c[i][j][k] = 0.0f;

    int kend = q0 + 64;
    for (int kc = 0; kc < kend; kc += KC) {
        for (int i = tid; i < 64*KC; i += 256) {
            int r = i >> 4, cc = i & 15;
            As[r][cc] = to_tf32(scb[(size_t)(b*NS + q0 + r)*NS + kc + cc]);
        }
        for (int i = tid; i < KC*64; i += 256) {
            int kk = i >> 6, n = i & 63;
            Bs[n][kk] = to_tf32(g_K[(b*NS + kc + kk)*ND2 + n0 + n]);
        }
        __syncthreads();
        #pragma unroll
        for (int ks = 0; ks < KC; ks += 8) {
            uint32_t a[2][4], bf[2][2];
            #pragma unroll
            for (int mf = 0; mf < 2; mf++) {
                int br = wm*32 + mf*16;
                a[mf][0] = __float_as_uint(As[br + g    ][ks + tg    ]);
                a[mf][1] = __float_as_uint(As[br + g + 8][ks + tg    ]);
                a[mf][2] = __float_as_uint(As[br + g    ][ks + tg + 4]);
                a[mf][3] = __float_as_uint(As[br + g + 8][ks + tg + 4]);
            }
            #pragma unroll
            for (int nf = 0; nf < 2; nf++) {
                int bc = wn*16 + nf*8 + g;
                bf[nf][0] = __float_as_uint(Bs[bc][ks + tg    ]);
                bf[nf][1] = __float_as_uint(Bs[bc][ks + tg + 4]);
            }
            #pragma unroll
            for (int mf = 0; mf < 2; mf++)
                #pragma unroll
                for (int nf = 0; nf < 2; nf++)
                    mma_tf32(c[mf][nf], a[mf], bf[nf]);
        }
        __syncthreads();
    }
    #pragma unroll
    for (int mf = 0; mf < 2; mf++) {
        #pragma unroll
        for (int nf = 0; nf < 2; nf++) {
            int row = q0 + wm*32 + mf*16 + g;
            int col = n0 + wn*16 + nf*8 + 2*tg;
            retb[(b*NS + row)*ND2 + col]       = c[mf][nf][0];
            retb[(b*NS + row)*ND2 + col + 1]   = c[mf][nf][1];
            retb[(b*NS + row + 8)*ND2 + col]     = c[mf][nf][2];
            retb[(b*NS + row + 8)*ND2 + col + 1] = c[mf][nf][3];
        }
    }
}

// ---------------- 3e+3f. fused EMA (both heads) + echo ----------------
// grid (NB, NL), block ND
__global__ void emaecho_kernel(const float* __restrict__ alpha,
                               const float* __restrict__ wout, const float* __restrict__ bout) {
    int b = blockIdx.x;
    int l = blockIdx.y;
    int d = threadIdx.x;
    const float* r0 = g_ret + (size_t)(l*NH + 0)*INST_RET;
    const float* r1 = g_ret + (size_t)(l*NH + 1)*INST_RET;
    float a0 = 1.0f / (1.0f + expf(-alpha[l*NH + 0]));
    float a1 = 1.0f / (1.0f + expf(-alpha[l*NH + 1]));
    float om0 = 1.0f - a0, om1 = 1.0f - a1;
    float wl = 1.0f + fabsf(wout[l*ND + d]);
    float rwl = 1.0f / wl;
    float bo = bout[l*ND + d];
    float* eo = g_echo + (size_t)l*LAY_X;
    float e10 = 0.0f, e20 = 0.0f, e11 = 0.0f, e21 = 0.0f;
    for (int t = 0; t < NS; t++) {
        int idx = (b*NS + t) * ND2;
        e10 = a0 * r0[idx + d]      + om0 * e10;
        e20 = a0 * r0[idx + ND + d] + om0 * e20;
        e11 = a1 * r1[idx + d]      + om1 * e11;
        e21 = a1 * r1[idx + ND + d] + om1 * e21;
        float v0 = e10 + e20;
        float v1 = e11 + e21;
        float comb = v0 + v1;
        float th = comb / wl + bo;
        (void)rwl;
        eo[(b*NS + t)*ND + d] = __cosf(th) + __sinf(th);
    }
}

// ---------------- 4a. FFN part 1 ----------------
#define SGRP 8
__global__ void ffn1_kernel(int l) {
    int blk = blockIdx.x;
    int b  = blk / (NS/SGRP);
    int s0 = (blk % (NS/SGRP)) * SGRP;
    __shared__ float xs[SGRP][ND];
    int tid = threadIdx.x;
    for (int i = tid; i < SGRP*ND; i += 256)
        xs[i/ND][i%ND] = g_x[(b*NS + s0 + i/ND)*ND + (i%ND)];
    __syncthreads();
    const float* rwT = g_rwT + l*ND*NN;
    const float* bT  = g_bT  + l*ND*NN;
    const float* acT = g_acT + l*ND*NN;
    const float* asT = g_asT + l*ND*NN;
    float sc[SGRP] = {}, ss[SGRP] = {};
    for (int d = 0; d < ND; d++) {
        float rw = rwT[d*NN + tid];
        float bb = bT [d*NN + tid];
        float ac = acT[d*NN + tid];
        float as = asT[d*NN + tid];
        #pragma unroll
        for (int s = 0; s < SGRP; s++) {
            float th = xs[s][d] * rw + bb;
            sc[s] += __cosf(th) * ac;
            ss[s] += __sinf(th) * as;
        }
    }
    #pragma unroll
    for (int s = 0; s < SGRP; s++) {
        g_cs[(b*NS + s0 + s)*NN + tid] = sc[s];
        g_ss[(b*NS + s0 + s)*NN + tid] = ss[s];
    }
}

// ---------------- 4b. FFN part 2 + silu + residual (+ bf16 split on last layer) ----------------
__global__ void ffn2_kernel(const float* __restrict__ pc, const float* __restrict__ ps,
                            const float* __restrict__ esc, const float* __restrict__ rsc,
                            int l, int do_split) {
    int m0 = blockIdx.x * 64;
    int n0 = blockIdx.y * 64;
    __shared__ float Ac[64][17], Asm[64][17], Pc[64][17], Ps[64][17];
    int tid = threadIdx.x;
    int ty = tid / 16, tx = tid % 16;
    float accc[4][4] = {}, accs[4][4] = {};
    const float* pcl = pc + l*ND*NN;
    const float* psl = ps + l*ND*NN;
    const float* echob = g_echo + (size_t)l*LAY_X;
    int r  = tid / 4;
    int c4 = (tid % 4) * 4;
    for (int kc = 0; kc < NN; kc += 16) {
        float4 v;
        v = *(const float4*)&g_cs[(m0 + r)*NN + kc + c4];
        Ac[r][c4+0]=v.x; Ac[r][c4+1]=v.y; Ac[r][c4+2]=v.z; Ac[r][c4+3]=v.w;
        v = *(const float4*)&g_ss[(m0 + r)*NN + kc + c4];
        Asm[r][c4+0]=v.x; Asm[r][c4+1]=v.y; Asm[r][c4+2]=v.z; Asm[r][c4+3]=v.w;
        v = *(const float4*)&pcl[(n0 + r)*NN + kc + c4];
        Pc[r][c4+0]=v.x; Pc[r][c4+1]=v.y; Pc[r][c4+2]=v.z; Pc[r][c4+3]=v.w;
        v = *(const float4*)&psl[(n0 + r)*NN + kc + c4];
        Ps[r][c4+0]=v.x; Ps[r][c4+1]=v.y; Ps[r][c4+2]=v.z; Ps[r][c4+3]=v.w;
        __syncthreads();
        #pragma unroll
        for (int kk = 0; kk < 16; kk++) {
            float a1[4], a2[4], b1[4], b2[4];
            #pragma unroll
            for (int i = 0; i < 4; i++) { a1[i] = Ac[ty*4+i][kk]; a2[i] = Asm[ty*4+i][kk]; }
            #pragma unroll
            for (int j = 0; j < 4; j++) { b1[j] = Pc[tx*4+j][kk]; b2[j] = Ps[tx*4+j][kk]; }
            #pragma unroll
            for (int i = 0; i < 4; i++)
                #pragma unroll
                for (int j = 0; j < 4; j++) {
                    accc[i][j] += a1[i]*b1[j];
                    accs[i][j] += a2[i]*b2[j];
                }
        }
        __syncthreads();
    }
    float es = esc[l], rs = rsc[l];
    #pragma unroll
    for (int i = 0; i < 4; i++) {
        int bs = m0 + ty*4 + i;
        #pragma unroll
        for (int j = 0; j < 4; j++) {
            int d = n0 + tx*4 + j;
            float o   = accc[i][j] + accs[i][j];
            float sig = 1.0f / (1.0f + __expf(-o));
            float res = o * sig;
            int xi = bs*ND + d;
            float nx = g_x[xi] + (es * echob[xi] + rs * res);
            g_x[xi] = nx;
            if (do_split) {
                __nv_bfloat16 h = __float2bfloat16(nx);
                g_xh[xi] = h;
                g_xl[xi] = __float2bfloat16(nx - __bfloat162float(h));
            }
        }
    }
}

// ---------------- 5. logits via 3xBF16-split m16n8k16 mma + ldmatrix, 128x128 tile ----------------
#define OKC 16
#define OKP (OKC+8)
__global__ __launch_bounds__(256) void out_mma_kernel(float* __restrict__ out) {
    __shared__ __nv_bfloat16 Ah[128][OKP], Al[128][OKP];
    __shared__ __nv_bfloat16 Bh[128][OKP], Bl[128][OKP];
    int tid = threadIdx.x;
    int wid = tid >> 5, lane = tid & 31;
    int wm = wid >> 2, wn = wid & 3;
    int n0 = blockIdx.x * 128;
    int m0 = blockIdx.y * 128;
    int g  = lane >> 2;
    int tg = lane & 3;
    int mrow = lane & 7;
    int msel = lane >> 3;            // 0..3
    int a_roff = ((msel & 1) << 3) + mrow;   // row offset within 16-row tile
    int a_coff = (msel & 2) << 2;            // 0 or 8 (k)
    int b_roff = ((msel & 2) << 2) + mrow;   // row offset within 16-row (two nf) tile
    int b_coff = (msel & 1) << 3;            // 0 or 8 (k)
    float c[4][4][4];
    #pragma unroll
    for (int a = 0; a < 4; a++)
        #pragma unroll
        for (int bq = 0; bq < 4; bq++)
            #pragma unroll
            for (int k = 0; k < 4; k++) c[a][bq][k] = 0.0f;

    for (int kc = 0; kc < ND; kc += OKC) {
        for (int i = tid; i < 128*8; i += 256) {
            int r = i >> 3, c2 = (i & 7) * 2;
            *(uint32_t*)&Ah[r][c2] = *(const uint32_t*)&g_xh [(m0 + r)*ND + kc + c2];
            *(uint32_t*)&Al[r][c2] = *(const uint32_t*)&g_xl [(m0 + r)*ND + kc + c2];
            *(uint32_t*)&Bh[r][c2] = *(const uint32_t*)&g_oph[(n0 + r)*ND + kc + c2];
            *(uint32_t*)&Bl[r][c2] = *(const uint32_t*)&g_opl[(n0 + r)*ND + kc + c2];
        }
        __syncthreads();
        uint32_t ah[4][4], al[4][4], bh[4][2], bl[4][2];
        #pragma unroll
        for (int mf = 0; mf < 4; mf++) {
            int r = wm*64 + mf*16 + a_roff;
            LDSM_X4(ah[mf][0], ah[mf][1], ah[mf][2], ah[mf][3], smem_u32(&Ah[r][a_coff]));
            LDSM_X4(al[mf][0], al[mf][1], al[mf][2], al[mf][3], smem_u32(&Al[r][a_coff]));
        }
        #pragma unroll
        for (int np = 0; np < 2; np++) {
            int r = wn*32 + np*16 + b_roff;
            LDSM_X4(bh[np*2][0], bh[np*2][1], bh[np*2+1][0], bh[np*2+1][1], smem_u32(&Bh[r][b_coff]));
            LDSM_X4(bl[np*2][0], bl[np*2][1], bl[np*2+1][0], bl[np*2+1][1], smem_u32(&Bl[r][b_coff]));
        }
        #pragma unroll
        for (int mf = 0; mf < 4; mf++)
            #pragma unroll
            for (int nf = 0; nf < 4; nf++) {
                mma_bf16(c[mf][nf], al[mf], bh[nf]);
                mma_bf16(c[mf][nf], ah[mf], bl[nf]);
                mma_bf16(c[mf][nf], ah[mf], bh[nf]);
            }
        __syncthreads();
    }
    #pragma unroll
    for (int mf = 0; mf < 4; mf++) {
        #pragma unroll
        for (int nf = 0; nf < 4; nf++) {
            int row = m0 + wm*64 + mf*16 + g;
            int col = n0 + wn*32 + nf*8 + 2*tg;
            out[row*NV + col]           = c[mf][nf][0];
            out[row*NV + col + 1]       = c[mf][nf][1];
            out[(row + 8)*NV + col]     = c[mf][nf][2];
            out[(row + 8)*NV + col + 1] = c[mf][nf][3];
        }
    }
}

// ---------------- launch ----------------
extern "C" void kernel_launch(void* const* d_in, const int* in_sizes, int n_in,
                              void* d_out, int out_size) {
    const int*   ids    = (const int*)  d_in[0];
    const float* embed  = (const float*)d_in[1];
    const float* wq     = (const float*)d_in[2];
    const float* bq     = (const float*)d_in[3];
    const float* alpha  = (const float*)d_in[4];
    const float* wout   = (const float*)d_in[5];
    const float* bout   = (const float*)d_in[6];
    const float* ffn_W  = (const float*)d_in[7];
    const float* ffn_B  = (const float*)d_in[8];
    const float* a_cos  = (const float*)d_in[9];
    const float* a_sin  = (const float*)d_in[10];
    const float* p_cos  = (const float*)d_in[11];
    const float* p_sin  = (const float*)d_in[12];
    const float* e_sc   = (const float*)d_in[13];
    const float* r_sc   = (const float*)d_in[14];
    const float* o_proj = (const float*)d_in[15];
    float* out = (float*)d_out;

    gather_kernel<<<(NB*NS*ND + 255)/256, 256>>>(ids, embed);
    scan_kernel<<<NB, ND>>>();
    ffnprep_kernel<<<(NL*NN*ND + 255)/256, 256>>>(ffn_W, ffn_B, a_cos, a_sin);
    opsplit_kernel<<<(NV*ND + 255)/256, 256>>>(o_proj);

    q_kernel<<<(NLH*NB*NS*ND + 255)/256, 256>>>(wq, bq);
    scores_mma_kernel<<<dim3(NS/64, NS/64, NB*NLH), 256>>>();
    softmax_kernel<<<dim3(NS, NB, NLH), 256>>>();
    av_mma_kernel<<<dim3(NS/64, ND2/64, NB*NLH), 256>>>();
    emaecho_kernel<<<dim3(NB, NL), ND>>>(alpha, wout, bout);

    for (int l = 0; l < NL; l++) {
        ffn1_kernel<<<NB*NS/SGRP, 256>>>(l);
        ffn2_kernel<<<dim3(NB*NS/64, ND/64), 256>>>(p_cos, p_sin, e_sc, r_sc, l, l == NL-1);
    }

    out_mma_kernel<<<dim3(NV/128, NB*NS/128), 256>>>(out);
}

// round 12
// speedup vs baseline: 1.2907x; 1.2907x over previous
#include <cuda_runtime.h>
#include <cuda_bf16.h>
#include <math.h>
#include <stdint.h>

#define NB 2
#define NS 1024
#define ND 128
#define ND2 256
#define NN 256
#define NH 2
#define NL 2
#define NLH (NL*NH)
#define NV 32000
#define PHI_F 1.6180339887498949f

#define INST_Q   (NB*NS*ND2)
#define INST_SC  ((size_t)NB*NS*NS)
#define INST_RET (NB*NS*ND2)
#define LAY_X    (NB*NS*ND)

// ---------------- scratch ----------------
static __device__ float g_wemb[NB*NS*ND];
static __device__ float g_bemb[NB*NS*ND];
static __device__ float g_sr  [NB*NS*ND];
static __device__ float g_si  [NB*NS*ND];
static __device__ float g_K   [NB*NS*ND2];
static __device__ float g_x   [NB*NS*ND];
static __device__ float g_Q   [NLH*INST_Q];
static __device__ float g_sc  [NLH*NB*NS*NS];
static __device__ float g_ret [NLH*INST_RET];
static __device__ float g_emah[NLH*LAY_X];
static __device__ float g_echo[NL*LAY_X];
static __device__ float g_cs  [NB*NS*NN];
static __device__ float g_ss  [NB*NS*NN];
static __device__ float g_rwT[NL*ND*NN];
static __device__ float g_bT [NL*ND*NN];
static __device__ float g_acT[NL*ND*NN];
static __device__ float g_asT[NL*ND*NN];
// bf16 hi/lo splits for logits GEMM
static __device__ __nv_bfloat16 g_oph[NV*ND];
static __device__ __nv_bfloat16 g_opl[NV*ND];
static __device__ __nv_bfloat16 g_xh [NB*NS*ND];
static __device__ __nv_bfloat16 g_xl [NB*NS*ND];

__device__ __forceinline__ float to_tf32(float v) {
    float r; asm("cvt.rna.tf32.f32 %0, %1;" : "=f"(r) : "f"(v)); return r;
}
__device__ __forceinline__ void mma_tf32(float* c, const uint32_t* a, const uint32_t* b) {
    asm volatile(
        "mma.sync.aligned.m16n8k8.row.col.f32.tf32.tf32.f32 "
        "{%0,%1,%2,%3},{%4,%5,%6,%7},{%8,%9},{%0,%1,%2,%3};"
        : "+f"(c[0]), "+f"(c[1]), "+f"(c[2]), "+f"(c[3])
        : "r"(a[0]), "r"(a[1]), "r"(a[2]), "r"(a[3]), "r"(b[0]), "r"(b[1]));
}
__device__ __forceinline__ void mma_bf16(float* c, const uint32_t* a, const uint32_t* b) {
    asm volatile(
        "mma.sync.aligned.m16n8k16.row.col.f32.bf16.bf16.f32 "
        "{%0,%1,%2,%3},{%4,%5,%6,%7},{%8,%9},{%0,%1,%2,%3};"
        : "+f"(c[0]), "+f"(c[1]), "+f"(c[2]), "+f"(c[3])
        : "r"(a[0]), "r"(a[1]), "r"(a[2]), "r"(a[3]), "r"(b[0]), "r"(b[1]));
}

// ---------------- 1. gather ----------------
__global__ void gather_kernel(const int* __restrict__ ids, const float* __restrict__ embed) {
    int i = blockIdx.x * blockDim.x + threadIdx.x;
    if (i >= NB*NS*ND) return;
    int d  = i % ND;
    int bs = i / ND;
    int tok = ids[bs];
    g_wemb[i] = embed[tok * ND2 + d];
    g_bemb[i] = embed[tok * ND2 + ND + d];
}

// ---------------- 2. euler scan, register-prefetched — numerics UNCHANGED ----------------
__global__ void scan_kernel() {
    int b = blockIdx.x;
    int d = threadIdx.x;
    float hr = 0.0f, hi = 0.0f;
    int base = b * NS * ND + d;
    float w  = g_wemb[base];
    float bb = g_bemb[base];
    for (int t = 0; t < NS; t++) {
        float wn = 0.0f, bn = 0.0f;
        if (t + 1 < NS) {
            wn = g_wemb[base + (t+1)*ND];
            bn = g_bemb[base + (t+1)*ND];
        }
        float wl = 1.0f + fabsf(w);
        float tphi = (float)t * PHI_F;
        float thr = hr / wl + bb + tphi;
        float thi = hi / wl + bb + tphi;
        float srv, crv, siv, civ;
        sincosf(thr, &srv, &crv);
        sincosf(thi, &siv, &civ);
        float nr = crv * civ - srv * siv;
        float ni = crv * siv + srv * civ;
        g_sr[base + t*ND] = nr;
        g_si[base + t*ND] = ni;
        g_x [base + t*ND] = nr + ni;
        int kb = (b*NS + t) * ND2;
        g_K[kb + d]      = nr;
        g_K[kb + ND + d] = ni;
        hr = nr; hi = ni;
        w = wn; bb = bn;
    }
}

// ---------------- weight prep ----------------
__global__ void ffnprep_kernel(const float* __restrict__ W, const float* __restrict__ Bp,
                               const float* __restrict__ ac, const float* __restrict__ as_) {
    int i = blockIdx.x * blockDim.x + threadIdx.x;
    if (i >= NL*NN*ND) return;
    int l = i / (NN*ND);
    int r = i % (NN*ND);
    int n = r / ND;
    int d = r % ND;
    int o = l*ND*NN + d*NN + n;
    g_rwT[o] = 1.0f / (1.0f + fabsf(W[i]));
    g_bT [o] = Bp[i];
    g_acT[o] = ac[i];
    g_asT[o] = as_[i];
}

__global__ void opsplit_kernel(const float* __restrict__ op) {
    int i = blockIdx.x * blockDim.x + threadIdx.x;
    if (i >= NV*ND) return;
    float v = op[i];
    __nv_bfloat16 h = __float2bfloat16(v);
    g_oph[i] = h;
    g_opl[i] = __float2bfloat16(v - __bfloat162float(h));
}

// ---------------- 3a. Q (MUFU cos; 1/16 scale folded in — exact pow2) ----------------
__global__ void q_kernel(const float* __restrict__ wq, const float* __restrict__ bq) {
    int i = blockIdx.x * blockDim.x + threadIdx.x;
    if (i >= NLH*NB*NS*ND) return;
    int inst = i / (NB*NS*ND);
    int j  = i % (NB*NS*ND);
    int d  = j % ND;
    int bs = j / ND;
    int t  = bs % NS;
    float wlq = 1.0f + fabsf(wq[inst*ND + d]);
    float bqv = bq[inst*ND + d];
    float tphi = (float)t * PHI_F;
    float thr = g_sr[j] / wlq + bqv + tphi;
    float thi = g_si[j] / wlq + bqv + tphi;
    float* Qb = g_Q + (size_t)inst*INST_Q;
    Qb[bs*ND2 + d]      = __cosf(thr) * 0.0625f;
    Qb[bs*ND2 + ND + d] = __cosf(thi) * 0.0625f;
}

// ---------------- 3b. scores via TF32 mma ----------------
#define KC 16
__global__ __launch_bounds__(256) void scores_mma_kernel() {
    int z = blockIdx.z;
    int b    = z % NB;
    int inst = z / NB;
    int q0 = blockIdx.x * 64;
    int k0 = blockIdx.y * 64;
    if (k0 > q0 + 63) return;
    const float* Qb = g_Q + (size_t)inst*INST_Q;
    float* scb = g_sc + (size_t)inst*INST_SC;
    __shared__ float Qs[64][KC+5];
    __shared__ float Ks[64][KC+5];
    int tid = threadIdx.x;
    int wid = tid >> 5, lane = tid & 31;
    int wm = wid >> 2, wn = wid & 3;
    int g  = lane >> 2, tg = lane & 3;
    float c[2][2][4];
    #pragma unroll
    for (int i = 0; i < 2; i++)
        #pragma unroll
        for (int j = 0; j < 2; j++)
            #pragma unroll
            for (int k = 0; k < 4; k++) c[i][j][k] = 0.0f;

    for (int kc = 0; kc < ND2; kc += KC) {
        for (int i = tid; i < 64*KC; i += 256) {
            int r = i >> 4, cc = i & 15;
            Qs[r][cc] = to_tf32(Qb[(b*NS + q0 + r)*ND2 + kc + cc]);
            Ks[r][cc] = to_tf32(g_K[(b*NS + k0 + r)*ND2 + kc + cc]);
        }
        __syncthreads();
        #pragma unroll
        for (int ks = 0; ks < KC; ks += 8) {
            uint32_t a[2][4], bf[2][2];
            #pragma unroll
            for (int mf = 0; mf < 2; mf++) {
                int br = wm*32 + mf*16;
                a[mf][0] = __float_as_uint(Qs[br + g    ][ks + tg    ]);
                a[mf][1] = __float_as_uint(Qs[br + g + 8][ks + tg    ]);
                a[mf][2] = __float_as_uint(Qs[br + g    ][ks + tg + 4]);
                a[mf][3] = __float_as_uint(Qs[br + g + 8][ks + tg + 4]);
            }
            #pragma unroll
            for (int nf = 0; nf < 2; nf++) {
                int bc = wn*16 + nf*8 + g;
                bf[nf][0] = __float_as_uint(Ks[bc][ks + tg    ]);
                bf[nf][1] = __float_as_uint(Ks[bc][ks + tg + 4]);
            }
            #pragma unroll
            for (int mf = 0; mf < 2; mf++)
                #pragma unroll
                for (int nf = 0; nf < 2; nf++)
                    mma_tf32(c[mf][nf], a[mf], bf[nf]);
        }
        __syncthreads();
    }
    #pragma unroll
    for (int mf = 0; mf < 2; mf++) {
        #pragma unroll
        for (int nf = 0; nf < 2; nf++) {
            int row = q0 + wm*32 + mf*16 + g;
            int col = k0 + wn*16 + nf*8 + 2*tg;
            size_t base0 = (size_t)(b*NS + row)*NS;
            size_t base1 = (size_t)(b*NS + row + 8)*NS;
            if (col     <= row)   scb[base0 + col]     = c[mf][nf][0];
            if (col + 1 <= row)   scb[base0 + col + 1] = c[mf][nf][1];
            if (col     <= row+8) scb[base1 + col]     = c[mf][nf][2];
            if (col + 1 <= row+8) scb[base1 + col + 1] = c[mf][nf][3];
        }
    }
}

// ---------------- 3c. single-pass softmax (scores bounded -> no max pass) ----------------
__global__ void softmax_kernel() {
    int q = blockIdx.x;
    int b = blockIdx.y;
    int inst = blockIdx.z;
    float* row = g_sc + (size_t)inst*INST_SC + (size_t)(b*NS + q)*NS;
    int tid = threadIdx.x;
    __shared__ float red[256];
    if (q == 0) {
        if (tid < 64) row[tid] = (tid == 0) ? 1.0f : 0.0f;
        return;
    }
    int len = q + 1;
    int kz_end = (q & ~63) + 64;
    float v[4];
    float sum = 0.0f;
    #pragma unroll
    for (int j = 0; j < 4; j++) {
        int k = tid + j*256;
        if (k < len) { v[j] = __expf(row[k]); sum += v[j]; }
        else v[j] = 0.0f;
    }
    red[tid] = sum; __syncthreads();
    for (int s = 128; s > 0; s >>= 1) { if (tid < s) red[tid] += red[tid+s]; __syncthreads(); }
    float inv = 1.0f / red[0];
    #pragma unroll
    for (int j = 0; j < 4; j++) {
        int k = tid + j*256;
        if (k < len)         row[k] = v[j] * inv;
        else if (k < kz_end) row[k] = 0.0f;
    }
}

// ---------------- 3d. retrieved = attn @ K via TF32 mma ----------------
__global__ __launch_bounds__(256) void av_mma_kernel() {
    int z = blockIdx.z;
    int b    = z % NB;
    int inst = z / NB;
    int q0 = blockIdx.x * 64;
    int n0 = blockIdx.y * 64;
    const float* scb = g_sc + (size_t)inst*INST_SC;
    float* retb = g_ret + (size_t)inst*INST_RET;
    __shared__ float As[64][KC+5];
    __shared__ float Bs[64][KC+5];
    int tid = threadIdx.x;
    int wid = tid >> 5, lane = tid & 31;
    int wm = wid >> 2, wn = wid & 3;
    int g  = lane >> 2, tg = lane & 3;
    float c[2][2][4];
    #pragma unroll
    for (int i = 0; i < 2; i++)
        #pragma unroll
        for (int j = 0; j < 2; j++)
            #pragma unroll
            for (int k = 0; k < 4; k++) c[i][j][k] = 0.0f;

    int kend = q0 + 64;
    for (int kc = 0; kc < kend; kc += KC) {
        for (int i = tid; i < 64*KC; i += 256) {
            int r = i >> 4, cc = i & 15;
            As[r][cc] = to_tf32(scb[(size_t)(b*NS + q0 + r)*NS + kc + cc]);
        }
        for (int i = tid; i < KC*64; i += 256) {
            int kk = i >> 6, n = i & 63;
            Bs[n][kk] = to_tf32(g_K[(b*NS + kc + kk)*ND2 + n0 + n]);
        }
        __syncthreads();
        #pragma unroll
        for (int ks = 0; ks < KC; ks += 8) {
            uint32_t a[2][4], bf[2][2];
            #pragma unroll
            for (int mf = 0; mf < 2; mf++) {
                int br = wm*32 + mf*16;
                a[mf][0] = __float_as_uint(As[br + g    ][ks + tg    ]);
                a[mf][1] = __float_as_uint(As[br + g + 8][ks + tg    ]);
                a[mf][2] = __float_as_uint(As[br + g    ][ks + tg + 4]);
                a[mf][3] = __float_as_uint(As[br + g + 8][ks + tg + 4]);
            }
            #pragma unroll
            for (int nf = 0; nf < 2; nf++) {
                int bc = wn*16 + nf*8 + g;
                bf[nf][0] = __float_as_uint(Bs[bc][ks + tg    ]);
                bf[nf][1] = __float_as_uint(Bs[bc][ks + tg + 4]);
            }
            #pragma unroll
            for (int mf = 0; mf < 2; mf++)
                #pragma unroll
                for (int nf = 0; nf < 2; nf++)
                    mma_tf32(c[mf][nf], a[mf], bf[nf]);
        }
        __syncthreads();
    }
    #pragma unroll
    for (int mf = 0; mf < 2; mf++) {
        #pragma unroll
        for (int nf = 0; nf < 2; nf++) {
            int row = q0 + wm*32 + mf*16 + g;
            int col = n0 + wn*16 + nf*8 + 2*tg;
            retb[(b*NS + row)*ND2 + col]       = c[mf][nf][0];
            retb[(b*NS + row)*ND2 + col + 1]   = c[mf][nf][1];
            retb[(b*NS + row + 8)*ND2 + col]     = c[mf][nf][2];
            retb[(b*NS + row + 8)*ND2 + col + 1] = c[mf][nf][3];
        }
    }
}

// ---------------- 3e. EMA — unroll-4 + register prefetch (bit-identical FMA order) ----------------
__global__ void ema_kernel(const float* __restrict__ alpha) {
    int b = blockIdx.x;
    int inst = blockIdx.y;
    int d = threadIdx.x;
    const float* retb = g_ret + (size_t)inst*INST_RET;
    float* eb = g_emah + (size_t)inst*LAY_X;
    float ap = alpha[inst];
    float a  = 1.0f / (1.0f + expf(-ap));
    float om = 1.0f - a;
    float e1 = 0.0f, e2 = 0.0f;
    for (int t0 = 0; t0 < NS; t0 += 4) {
        float r1v[4], r2v[4];
        #pragma unroll
        for (int j = 0; j < 4; j++) {
            int idx = (b*NS + t0 + j) * ND2;
            r1v[j] = retb[idx + d];
            r2v[j] = retb[idx + ND + d];
        }
        #pragma unroll
        for (int j = 0; j < 4; j++) {
            e1 = a * r1v[j] + om * e1;
            e2 = a * r2v[j] + om * e2;
            eb[(b*NS + t0 + j)*ND + d] = e1 + e2;
        }
    }
}

// ---------------- 3f. echo ----------------
__global__ void echo_kernel(const float* __restrict__ wout, const float* __restrict__ bout) {
    int i = blockIdx.x * blockDim.x + threadIdx.x;
    if (i >= NL*NB*NS*ND) return;
    int l = i / LAY_X;
    int j = i % LAY_X;
    int d = j % ND;
    float comb = g_emah[(size_t)(l*NH + 0)*LAY_X + j] + g_emah[(size_t)(l*NH + 1)*LAY_X + j];
    float wl = 1.0f + fabsf(wout[l*ND + d]);
    float th = comb / wl + bout[l*ND + d];
    g_echo[(size_t)l*LAY_X + j] = __cosf(th) + __sinf(th);
}

// ---------------- 4a. FFN part 1 ----------------
#define SGRP 8
__global__ void ffn1_kernel(int l) {
    int blk = blockIdx.x;
    int b  = blk / (NS/SGRP);
    int s0 = (blk % (NS/SGRP)) * SGRP;
    __shared__ float xs[SGRP][ND];
    int tid = threadIdx.x;
    for (int i = tid; i < SGRP*ND; i += 256)
        xs[i/ND][i%ND] = g_x[(b*NS + s0 + i/ND)*ND + (i%ND)];
    __syncthreads();
    const float* rwT = g_rwT + l*ND*NN;
    const float* bT  = g_bT  + l*ND*NN;
    const float* acT = g_acT + l*ND*NN;
    const float* asT = g_asT + l*ND*NN;
    float sc[SGRP] = {}, ss[SGRP] = {};
    for (int d = 0; d < ND; d++) {
        float rw = rwT[d*NN + tid];
        float bb = bT [d*NN + tid];
        float ac = acT[d*NN + tid];
        float as = asT[d*NN + tid];
        #pragma unroll
        for (int s = 0; s < SGRP; s++) {
            float th = xs[s][d] * rw + bb;
            sc[s] += __cosf(th) * ac;
            ss[s] += __sinf(th) * as;
        }
    }
    #pragma unroll
    for (int s = 0; s < SGRP; s++) {
        g_cs[(b*NS + s0 + s)*NN + tid] = sc[s];
        g_ss[(b*NS + s0 + s)*NN + tid] = ss[s];
    }
}

// ---------------- 4b. FFN part 2 + silu + residual (+ bf16 split on last layer) ----------------
__global__ void ffn2_kernel(const float* __restrict__ pc, const float* __restrict__ ps,
                            const float* __restrict__ esc, const float* __restrict__ rsc,
                            int l, int do_split) {
    int m0 = blockIdx.x * 64;
    int n0 = blockIdx.y * 64;
    __shared__ float Ac[64][17], Asm[64][17], Pc[64][17], Ps[64][17];
    int tid = threadIdx.x;
    int ty = tid / 16, tx = tid % 16;
    float accc[4][4] = {}, accs[4][4] = {};
    const float* pcl = pc + l*ND*NN;
    const float* psl = ps + l*ND*NN;
    const float* echob = g_echo + (size_t)l*LAY_X;
    int r  = tid / 4;
    int c4 = (tid % 4) * 4;
    for (int kc = 0; kc < NN; kc += 16) {
        float4 v;
        v = *(const float4*)&g_cs[(m0 + r)*NN + kc + c4];
        Ac[r][c4+0]=v.x; Ac[r][c4+1]=v.y; Ac[r][c4+2]=v.z; Ac[r][c4+3]=v.w;
        v = *(const float4*)&g_ss[(m0 + r)*NN + kc + c4];
        Asm[r][c4+0]=v.x; Asm[r][c4+1]=v.y; Asm[r][c4+2]=v.z; Asm[r][c4+3]=v.w;
        v = *(const float4*)&pcl[(n0 + r)*NN + kc + c4];
        Pc[r][c4+0]=v.x; Pc[r][c4+1]=v.y; Pc[r][c4+2]=v.z; Pc[r][c4+3]=v.w;
        v = *(const float4*)&psl[(n0 + r)*NN + kc + c4];
        Ps[r][c4+0]=v.x; Ps[r][c4+1]=v.y; Ps[r][c4+2]=v.z; Ps[r][c4+3]=v.w;
        __syncthreads();
        #pragma unroll
        for (int kk = 0; kk < 16; kk++) {
            float a1[4], a2[4], b1[4], b2[4];
            #pragma unroll
            for (int i = 0; i < 4; i++) { a1[i] = Ac[ty*4+i][kk]; a2[i] = Asm[ty*4+i][kk]; }
            #pragma unroll
            for (int j = 0; j < 4; j++) { b1[j] = Pc[tx*4+j][kk]; b2[j] = Ps[tx*4+j][kk]; }
            #pragma unroll
            for (int i = 0; i < 4; i++)
                #pragma unroll
                for (int j = 0; j < 4; j++) {
                    accc[i][j] += a1[i]*b1[j];
                    accs[i][j] += a2[i]*b2[j];
                }
        }
        __syncthreads();
    }
    float es = esc[l], rs = rsc[l];
    #pragma unroll
    for (int i = 0; i < 4; i++) {
        int bs = m0 + ty*4 + i;
        #pragma unroll
        for (int j = 0; j < 4; j++) {
            int d = n0 + tx*4 + j;
            float o   = accc[i][j] + accs[i][j];
            float sig = 1.0f / (1.0f + __expf(-o));
            float res = o * sig;
            int xi = bs*ND + d;
            float nx = g_x[xi] + (es * echob[xi] + rs * res);
            g_x[xi] = nx;
            if (do_split) {
                __nv_bfloat16 h = __float2bfloat16(nx);
                g_xh[xi] = h;
                g_xl[xi] = __float2bfloat16(nx - __bfloat162float(h));
            }
        }
    }
}

// ---------------- 5. logits via 3xBF16-split m16n8k16 mma, 128x128 tile (R8 scalar loads) ----------------
#define OKC 16
#define OKP (OKC+8)
__global__ __launch_bounds__(256) void out_mma_kernel(float* __restrict__ out) {
    __shared__ __nv_bfloat16 Ah[128][OKP], Al[128][OKP];
    __shared__ __nv_bfloat16 Bh[128][OKP], Bl[128][OKP];
    int tid = threadIdx.x;
    int wid = tid >> 5, lane = tid & 31;
    int wm = wid >> 2, wn = wid & 3;
    int n0 = blockIdx.x * 128;
    int m0 = blockIdx.y * 128;
    int g  = lane >> 2;
    int tg = lane & 3;
    float c[4][4][4];
    #pragma unroll
    for (int a = 0; a < 4; a++)
        #pragma unroll
        for (int bq = 0; bq < 4; bq++)
            #pragma unroll
            for (int k = 0; k < 4; k++) c[a][bq][k] = 0.0f;

    for (int kc = 0; kc < ND; kc += OKC) {
        for (int i = tid; i < 128*8; i += 256) {
            int r = i >> 3, c2 = (i & 7) * 2;
            *(uint32_t*)&Ah[r][c2] = *(const uint32_t*)&g_xh [(m0 + r)*ND + kc + c2];
            *(uint32_t*)&Al[r][c2] = *(const uint32_t*)&g_xl [(m0 + r)*ND + kc + c2];
            *(uint32_t*)&Bh[r][c2] = *(const uint32_t*)&g_oph[(n0 + r)*ND + kc + c2];
            *(uint32_t*)&Bl[r][c2] = *(const uint32_t*)&g_opl[(n0 + r)*ND + kc + c2];
        }
        __syncthreads();
        uint32_t ah[4][4], al[4][4], bh[4][2], bl[4][2];
        #pragma unroll
        for (int mf = 0; mf < 4; mf++) {
            int br = wm*64 + mf*16;
            ah[mf][0] = *(const uint32_t*)&Ah[br + g    ][tg*2    ];
            ah[mf][1] = *(const uint32_t*)&Ah[br + g + 8][tg*2    ];
            ah[mf][2] = *(const uint32_t*)&Ah[br + g    ][tg*2 + 8];
            ah[mf][3] = *(const uint32_t*)&Ah[br + g + 8][tg*2 + 8];
            al[mf][0] = *(const uint32_t*)&Al[br + g    ][tg*2    ];
            al[mf][1] = *(const uint32_t*)&Al[br + g + 8][tg*2    ];
            al[mf][2] = *(const uint32_t*)&Al[br + g    ][tg*2 + 8];
            al[mf][3] = *(const uint32_t*)&Al[br + g + 8][tg*2 + 8];
        }
        #pragma unroll
        for (int nf = 0; nf < 4; nf++) {
            int bc = wn*32 + nf*8 + g;
            bh[nf][0] = *(const uint32_t*)&Bh[bc][tg*2    ];
            bh[nf][1] = *(const uint32_t*)&Bh[bc][tg*2 + 8];
            bl[nf][0] = *(const uint32_t*)&Bl[bc][tg*2    ];
            bl[nf][1] = *(const uint32_t*)&Bl[bc][tg*2 + 8];
        }
        #pragma unroll
        for (int mf = 0; mf < 4; mf++)
            #pragma unroll
            for (int nf = 0; nf < 4; nf++) {
                mma_bf16(c[mf][nf], al[mf], bh[nf]);
                mma_bf16(c[mf][nf], ah[mf], bl[nf]);
                mma_bf16(c[mf][nf], ah[mf], bh[nf]);
            }
        __syncthreads();
    }
    #pragma unroll
    for (int mf = 0; mf < 4; mf++) {
        #pragma unroll
        for (int nf = 0; nf < 4; nf++) {
            int row = m0 + wm*64 + mf*16 + g;
            int col = n0 + wn*32 + nf*8 + 2*tg;
            out[row*NV + col]           = c[mf][nf][0];
            out[row*NV + col + 1]       = c[mf][nf][1];
            out[(row + 8)*NV + col]     = c[mf][nf][2];
            out[(row + 8)*NV + col + 1] = c[mf][nf][3];
        }
    }
}

// ---------------- launch ----------------
extern "C" void kernel_launch(void* const* d_in, const int* in_sizes, int n_in,
                              void* d_out, int out_size) {
    const int*   ids    = (const int*)  d_in[0];
    const float* embed  = (const float*)d_in[1];
    const float* wq     = (const float*)d_in[2];
    const float* bq     = (const float*)d_in[3];
    const float* alpha  = (const float*)d_in[4];
    const float* wout   = (const float*)d_in[5];
    const float* bout   = (const float*)d_in[6];
    const float* ffn_W  = (const float*)d_in[7];
    const float* ffn_B  = (const float*)d_in[8];
    const float* a_cos  = (const float*)d_in[9];
    const float* a_sin  = (const float*)d_in[10];
    const float* p_cos  = (const float*)d_in[11];
    const float* p_sin  = (const float*)d_in[12];
    const float* e_sc   = (const float*)d_in[13];
    const float* r_sc   = (const float*)d_in[14];
    const float* o_proj = (const float*)d_in[15];
    float* out = (float*)d_out;

    gather_kernel<<<(NB*NS*ND + 255)/256, 256>>>(ids, embed);
    scan_kernel<<<NB, ND>>>();
    ffnprep_kernel<<<(NL*NN*ND + 255)/256, 256>>>(ffn_W, ffn_B, a_cos, a_sin);
    opsplit_kernel<<<(NV*ND + 255)/256, 256>>>(o_proj);

    q_kernel<<<(NLH*NB*NS*ND + 255)/256, 256>>>(wq, bq);
    scores_mma_kernel<<<dim3(NS/64, NS/64, NB*NLH), 256>>>();
    softmax_kernel<<<dim3(NS, NB, NLH), 256>>>();
    av_mma_kernel<<<dim3(NS/64, ND2/64, NB*NLH), 256>>>();
    ema_kernel<<<dim3(NB, NLH), ND>>>(alpha);
    echo_kernel<<<(NL*NB*NS*ND + 255)/256, 256>>>(wout, bout);

    for (int l = 0; l < NL; l++) {
        ffn1_kernel<<<NB*NS/SGRP, 256>>>(l);
        ffn2_kernel<<<dim3(NB*NS/64, ND/64), 256>>>(p_cos, p_sin, e_sc, r_sc, l, l == NL-1);
    }

    out_mma_kernel<<<dim3(NV/128, NB*NS/128), 256>>>(out);
}

// round 13
// speedup vs baseline: 1.2977x; 1.0054x over previous
#include <cuda_runtime.h>
#include <cuda_bf16.h>
#include <math.h>
#include <stdint.h>

#define NB 2
#define NS 1024
#define ND 128
#define ND2 256
#define NN 256
#define NH 2
#define NL 2
#define NLH (NL*NH)
#define NV 32000
#define PHI_F 1.6180339887498949f

#define INST_Q   (NB*NS*ND2)
#define INST_SC  ((size_t)NB*NS*NS)
#define INST_RET (NB*NS*ND2)
#define LAY_X    (NB*NS*ND)

// ---------------- scratch ----------------
static __device__ float g_wemb[NB*NS*ND];
static __device__ float g_bemb[NB*NS*ND];
static __device__ float g_sr  [NB*NS*ND];
static __device__ float g_si  [NB*NS*ND];
static __device__ float g_K   [NB*NS*ND2];
static __device__ float g_x   [NB*NS*ND];
static __device__ float g_Q   [NLH*INST_Q];
static __device__ float g_sc  [NLH*NB*NS*NS];
static __device__ float g_ret [NLH*INST_RET];
static __device__ float g_emah[NLH*LAY_X];
static __device__ float g_echo[NL*LAY_X];
static __device__ float g_cs  [NB*NS*NN];
static __device__ float g_ss  [NB*NS*NN];
static __device__ float g_rwT[NL*ND*NN];
static __device__ float g_bT [NL*ND*NN];
static __device__ float g_acT[NL*ND*NN];
static __device__ float g_asT[NL*ND*NN];
// bf16 hi/lo splits for logits GEMM
static __device__ __nv_bfloat16 g_oph[NV*ND];
static __device__ __nv_bfloat16 g_opl[NV*ND];
static __device__ __nv_bfloat16 g_xh [NB*NS*ND];
static __device__ __nv_bfloat16 g_xl [NB*NS*ND];

__device__ __forceinline__ float to_tf32(float v) {
    float r; asm("cvt.rna.tf32.f32 %0, %1;" : "=f"(r) : "f"(v)); return r;
}
__device__ __forceinline__ void mma_tf32(float* c, const uint32_t* a, const uint32_t* b) {
    asm volatile(
        "mma.sync.aligned.m16n8k8.row.col.f32.tf32.tf32.f32 "
        "{%0,%1,%2,%3},{%4,%5,%6,%7},{%8,%9},{%0,%1,%2,%3};"
        : "+f"(c[0]), "+f"(c[1]), "+f"(c[2]), "+f"(c[3])
        : "r"(a[0]), "r"(a[1]), "r"(a[2]), "r"(a[3]), "r"(b[0]), "r"(b[1]));
}
__device__ __forceinline__ void mma_bf16(float* c, const uint32_t* a, const uint32_t* b) {
    asm volatile(
        "mma.sync.aligned.m16n8k16.row.col.f32.bf16.bf16.f32 "
        "{%0,%1,%2,%3},{%4,%5,%6,%7},{%8,%9},{%0,%1,%2,%3};"
        : "+f"(c[0]), "+f"(c[1]), "+f"(c[2]), "+f"(c[3])
        : "r"(a[0]), "r"(a[1]), "r"(a[2]), "r"(a[3]), "r"(b[0]), "r"(b[1]));
}

// ---------------- 1. gather ----------------
__global__ void gather_kernel(const int* __restrict__ ids, const float* __restrict__ embed) {
    int i = blockIdx.x * blockDim.x + threadIdx.x;
    if (i >= NB*NS*ND) return;
    int d  = i % ND;
    int bs = i / ND;
    int tok = ids[bs];
    g_wemb[i] = embed[tok * ND2 + d];
    g_bemb[i] = embed[tok * ND2 + ND + d];
}

// ---------------- 2. euler scan, register-prefetched — numerics UNCHANGED ----------------
__global__ void scan_kernel() {
    int b = blockIdx.x;
    int d = threadIdx.x;
    float hr = 0.0f, hi = 0.0f;
    int base = b * NS * ND + d;
    float w  = g_wemb[base];
    float bb = g_bemb[base];
    for (int t = 0; t < NS; t++) {
        float wn = 0.0f, bn = 0.0f;
        if (t + 1 < NS) {
            wn = g_wemb[base + (t+1)*ND];
            bn = g_bemb[base + (t+1)*ND];
        }
        float wl = 1.0f + fabsf(w);
        float tphi = (float)t * PHI_F;
        float thr = hr / wl + bb + tphi;
        float thi = hi / wl + bb + tphi;
        float srv, crv, siv, civ;
        sincosf(thr, &srv, &crv);
        sincosf(thi, &siv, &civ);
        float nr = crv * civ - srv * siv;
        float ni = crv * siv + srv * civ;
        g_sr[base + t*ND] = nr;
        g_si[base + t*ND] = ni;
        g_x [base + t*ND] = nr + ni;
        int kb = (b*NS + t) * ND2;
        g_K[kb + d]      = nr;
        g_K[kb + ND + d] = ni;
        hr = nr; hi = ni;
        w = wn; bb = bn;
    }
}

// ---------------- weight prep ----------------
__global__ void ffnprep_kernel(const float* __restrict__ W, const float* __restrict__ Bp,
                               const float* __restrict__ ac, const float* __restrict__ as_) {
    int i = blockIdx.x * blockDim.x + threadIdx.x;
    if (i >= NL*NN*ND) return;
    int l = i / (NN*ND);
    int r = i % (NN*ND);
    int n = r / ND;
    int d = r % ND;
    int o = l*ND*NN + d*NN + n;
    g_rwT[o] = 1.0f / (1.0f + fabsf(W[i]));
    g_bT [o] = Bp[i];
    g_acT[o] = ac[i];
    g_asT[o] = as_[i];
}

// vectorized x2 (element-wise conversion identical)
__global__ void opsplit_kernel(const float* __restrict__ op) {
    int i = (blockIdx.x * blockDim.x + threadIdx.x) * 2;
    if (i >= NV*ND) return;
    float2 v = *(const float2*)&op[i];
    __nv_bfloat16 h0 = __float2bfloat16(v.x);
    __nv_bfloat16 h1 = __float2bfloat16(v.y);
    __nv_bfloat16 l0 = __float2bfloat16(v.x - __bfloat162float(h0));
    __nv_bfloat16 l1 = __float2bfloat16(v.y - __bfloat162float(h1));
    __nv_bfloat162 hp; hp.x = h0; hp.y = h1;
    __nv_bfloat162 lp; lp.x = l0; lp.y = l1;
    *(__nv_bfloat162*)&g_oph[i] = hp;
    *(__nv_bfloat162*)&g_opl[i] = lp;
}

// ---------------- 3a. Q (MUFU cos; 1/16 scale folded in — exact pow2) ----------------
__global__ void q_kernel(const float* __restrict__ wq, const float* __restrict__ bq) {
    int i = blockIdx.x * blockDim.x + threadIdx.x;
    if (i >= NLH*NB*NS*ND) return;
    int inst = i / (NB*NS*ND);
    int j  = i % (NB*NS*ND);
    int d  = j % ND;
    int bs = j / ND;
    int t  = bs % NS;
    float wlq = 1.0f + fabsf(wq[inst*ND + d]);
    float bqv = bq[inst*ND + d];
    float tphi = (float)t * PHI_F;
    float thr = g_sr[j] / wlq + bqv + tphi;
    float thi = g_si[j] / wlq + bqv + tphi;
    float* Qb = g_Q + (size_t)inst*INST_Q;
    Qb[bs*ND2 + d]      = __cosf(thr) * 0.0625f;
    Qb[bs*ND2 + ND + d] = __cosf(thi) * 0.0625f;
}

// ---------------- 3b. scores via TF32 mma ----------------
#define KC 16
__global__ __launch_bounds__(256) void scores_mma_kernel() {
    int z = blockIdx.z;
    int b    = z % NB;
    int inst = z / NB;
    int q0 = blockIdx.x * 64;
    int k0 = blockIdx.y * 64;
    if (k0 > q0 + 63) return;
    const float* Qb = g_Q + (size_t)inst*INST_Q;
    float* scb = g_sc + (size_t)inst*INST_SC;
    __shared__ float Qs[64][KC+5];
    __shared__ float Ks[64][KC+5];
    int tid = threadIdx.x;
    int wid = tid >> 5, lane = tid & 31;
    int wm = wid >> 2, wn = wid & 3;
    int g  = lane >> 2, tg = lane & 3;
    float c[2][2][4];
    #pragma unroll
    for (int i = 0; i < 2; i++)
        #pragma unroll
        for (int j = 0; j < 2; j++)
            #pragma unroll
            for (int k = 0; k < 4; k++) c[i][j][k] = 0.0f;

    for (int kc = 0; kc < ND2; kc += KC) {
        for (int i = tid; i < 64*KC; i += 256) {
            int r = i >> 4, cc = i & 15;
            Qs[r][cc] = to_tf32(Qb[(b*NS + q0 + r)*ND2 + kc + cc]);
            Ks[r][cc] = to_tf32(g_K[(b*NS + k0 + r)*ND2 + kc + cc]);
        }
        __syncthreads();
        #pragma unroll
        for (int ks = 0; ks < KC; ks += 8) {
            uint32_t a[2][4], bf[2][2];
            #pragma unroll
            for (int mf = 0; mf < 2; mf++) {
                int br = wm*32 + mf*16;
                a[mf][0] = __float_as_uint(Qs[br + g    ][ks + tg    ]);
                a[mf][1] = __float_as_uint(Qs[br + g + 8][ks + tg    ]);
                a[mf][2] = __float_as_uint(Qs[br + g    ][ks + tg + 4]);
                a[mf][3] = __float_as_uint(Qs[br + g + 8][ks + tg + 4]);
            }
            #pragma unroll
            for (int nf = 0; nf < 2; nf++) {
                int bc = wn*16 + nf*8 + g;
                bf[nf][0] = __float_as_uint(Ks[bc][ks + tg    ]);
                bf[nf][1] = __float_as_uint(Ks[bc][ks + tg + 4]);
            }
            #pragma unroll
            for (int mf = 0; mf < 2; mf++)
                #pragma unroll
                for (int nf = 0; nf < 2; nf++)
                    mma_tf32(c[mf][nf], a[mf], bf[nf]);
        }
        __syncthreads();
    }
    #pragma unroll
    for (int mf = 0; mf < 2; mf++) {
        #pragma unroll
        for (int nf = 0; nf < 2; nf++) {
            int row = q0 + wm*32 + mf*16 + g;
            int col = k0 + wn*16 + nf*8 + 2*tg;
            size_t base0 = (size_t)(b*NS + row)*NS;
            size_t base1 = (size_t)(b*NS + row + 8)*NS;
            if (col     <= row)   scb[base0 + col]     = c[mf][nf][0];
            if (col + 1 <= row)   scb[base0 + col + 1] = c[mf][nf][1];
            if (col     <= row+8) scb[base1 + col]     = c[mf][nf][2];
            if (col + 1 <= row+8) scb[base1 + col + 1] = c[mf][nf][3];
        }
    }
}

// ---------------- 3c. softmax: 4 rows/block, 64 threads/row, shfl reductions ----------------
// grid (NS/4, NB, NLH), block 256
__global__ void softmax_kernel() {
    int tid = threadIdx.x;
    int gr = tid >> 6, lt = tid & 63;
    int q = blockIdx.x * 4 + gr;
    int b = blockIdx.y;
    int inst = blockIdx.z;
    float* row = g_sc + (size_t)inst*INST_SC + (size_t)(b*NS + q)*NS;
    __shared__ float wsum[8];
    bool isq0 = (q == 0);
    int len = q + 1;
    int kz_end = (q & ~63) + 64;
    float v[16];
    float sum = 0.0f;
    if (!isq0) {
        #pragma unroll
        for (int j = 0; j < 16; j++) {
            int k = lt + j*64;
            if (k < len) { v[j] = __expf(row[k]); sum += v[j]; }
            else v[j] = 0.0f;
        }
    }
    #pragma unroll
    for (int o = 16; o > 0; o >>= 1) sum += __shfl_xor_sync(0xffffffffu, sum, o);
    if ((tid & 31) == 0) wsum[tid >> 5] = sum;
    __syncthreads();
    if (isq0) {
        row[lt] = (lt == 0) ? 1.0f : 0.0f;   // kz_end = 64 exactly
    } else {
        float inv = 1.0f / (wsum[gr*2] + wsum[gr*2 + 1]);
        #pragma unroll
        for (int j = 0; j < 16; j++) {
            int k = lt + j*64;
            if (k < len)         row[k] = v[j] * inv;
            else if (k < kz_end) row[k] = 0.0f;
        }
    }
}

// ---------------- 3d. retrieved = attn @ K via TF32 mma ----------------
__global__ __launch_bounds__(256) void av_mma_kernel() {
    int z = blockIdx.z;
    int b    = z % NB;
    int inst = z / NB;
    int q0 = blockIdx.x * 64;
    int n0 = blockIdx.y * 64;
    const float* scb = g_sc + (size_t)inst*INST_SC;
    float* retb = g_ret + (size_t)inst*INST_RET;
    __shared__ float As[64][KC+5];
    __shared__ float Bs[64][KC+5];
    int tid = threadIdx.x;
    int wid = tid >> 5, lane = tid & 31;
    int wm = wid >> 2, wn = wid & 3;
    int g  = lane >> 2, tg = lane & 3;
    float c[2][2][4];
    #pragma unroll
    for (int i = 0; i < 2; i++)
        #pragma unroll
        for (int j = 0; j < 2; j++)
            #pragma unroll
            for (int k = 0; k < 4; k++) c[i][j][k] = 0.0f;

    int kend = q0 + 64;
    for (int kc = 0; kc < kend; kc += KC) {
        for (int i = tid; i < 64*KC; i += 256) {
            int r = i >> 4, cc = i & 15;
            As[r][cc] = to_tf32(scb[(size_t)(b*NS + q0 + r)*NS + kc + cc]);
        }
        for (int i = tid; i < KC*64; i += 256) {
            int kk = i >> 6, n = i & 63;
            Bs[n][kk] = to_tf32(g_K[(b*NS + kc + kk)*ND2 + n0 + n]);
        }
        __syncthreads();
        #pragma unroll
        for (int ks = 0; ks < KC; ks += 8) {
            uint32_t a[2][4], bf[2][2];
            #pragma unroll
            for (int mf = 0; mf < 2; mf++) {
                int br = wm*32 + mf*16;
                a[mf][0] = __float_as_uint(As[br + g    ][ks + tg    ]);
                a[mf][1] = __float_as_uint(As[br + g + 8][ks + tg    ]);
                a[mf][2] = __float_as_uint(As[br + g    ][ks + tg + 4]);
                a[mf][3] = __float_as_uint(As[br + g + 8][ks + tg + 4]);
            }
            #pragma unroll
            for (int nf = 0; nf < 2; nf++) {
                int bc = wn*16 + nf*8 + g;
                bf[nf][0] = __float_as_uint(Bs[bc][ks + tg    ]);
                bf[nf][1] = __float_as_uint(Bs[bc][ks + tg + 4]);
            }
            #pragma unroll
            for (int mf = 0; mf < 2; mf++)
                #pragma unroll
                for (int nf = 0; nf < 2; nf++)
                    mma_tf32(c[mf][nf], a[mf], bf[nf]);
        }
        __syncthreads();
    }
    #pragma unroll
    for (int mf = 0; mf < 2; mf++) {
        #pragma unroll
        for (int nf = 0; nf < 2; nf++) {
            int row = q0 + wm*32 + mf*16 + g;
            int col = n0 + wn*16 + nf*8 + 2*tg;
            retb[(b*NS + row)*ND2 + col]       = c[mf][nf][0];
            retb[(b*NS + row)*ND2 + col + 1]   = c[mf][nf][1];
            retb[(b*NS + row + 8)*ND2 + col]     = c[mf][nf][2];
            retb[(b*NS + row + 8)*ND2 + col + 1] = c[mf][nf][3];
        }
    }
}

// ---------------- 3e. EMA — unroll-4 + register prefetch (bit-identical FMA order) ----------------
__global__ void ema_kernel(const float* __restrict__ alpha) {
    int b = blockIdx.x;
    int inst = blockIdx.y;
    int d = threadIdx.x;
    const float* retb = g_ret + (size_t)inst*INST_RET;
    float* eb = g_emah + (size_t)inst*LAY_X;
    float ap = alpha[inst];
    float a  = 1.0f / (1.0f + expf(-ap));
    float om = 1.0f - a;
    float e1 = 0.0f, e2 = 0.0f;
    for (int t0 = 0; t0 < NS; t0 += 4) {
        float r1v[4], r2v[4];
        #pragma unroll
        for (int j = 0; j < 4; j++) {
            int idx = (b*NS + t0 + j) * ND2;
            r1v[j] = retb[idx + d];
            r2v[j] = retb[idx + ND + d];
        }
        #pragma unroll
        for (int j = 0; j < 4; j++) {
            e1 = a * r1v[j] + om * e1;
            e2 = a * r2v[j] + om * e2;
            eb[(b*NS + t0 + j)*ND + d] = e1 + e2;
        }
    }
}

// ---------------- 3f. echo (sincosf pairing — same RRO+MUFU values) ----------------
__global__ void echo_kernel(const float* __restrict__ wout, const float* __restrict__ bout) {
    int i = blockIdx.x * blockDim.x + threadIdx.x;
    if (i >= NL*NB*NS*ND) return;
    int l = i / LAY_X;
    int j = i % LAY_X;
    int d = j % ND;
    float comb = g_emah[(size_t)(l*NH + 0)*LAY_X + j] + g_emah[(size_t)(l*NH + 1)*LAY_X + j];
    float wl = 1.0f + fabsf(wout[l*ND + d]);
    float th = comb / wl + bout[l*ND + d];
    float sv, cv; __sincosf(th, &sv, &cv);
    g_echo[(size_t)l*LAY_X + j] = cv + sv;
}

// ---------------- 4a. FFN part 1 (__sincosf: shared RRO) ----------------
#define SGRP 8
__global__ void ffn1_kernel(int l) {
    int blk = blockIdx.x;
    int b  = blk / (NS/SGRP);
    int s0 = (blk % (NS/SGRP)) * SGRP;
    __shared__ float xs[SGRP][ND];
    int tid = threadIdx.x;
    for (int i = tid; i < SGRP*ND; i += 256)
        xs[i/ND][i%ND] = g_x[(b*NS + s0 + i/ND)*ND + (i%ND)];
    __syncthreads();
    const float* rwT = g_rwT + l*ND*NN;
    const float* bT  = g_bT  + l*ND*NN;
    const float* acT = g_acT + l*ND*NN;
    const float* asT = g_asT + l*ND*NN;
    float sc[SGRP] = {}, ss[SGRP] = {};
    for (int d = 0; d < ND; d++) {
        float rw = rwT[d*NN + tid];
        float bb = bT [d*NN + tid];
        float ac = acT[d*NN + tid];
        float as = asT[d*NN + tid];
        #pragma unroll
        for (int s = 0; s < SGRP; s++) {
            float th = xs[s][d] * rw + bb;
            float sv, cv; __sincosf(th, &sv, &cv);
            sc[s] += cv * ac;
            ss[s] += sv * as;
        }
    }
    #pragma unroll
    for (int s = 0; s < SGRP; s++) {
        g_cs[(b*NS + s0 + s)*NN + tid] = sc[s];
        g_ss[(b*NS + s0 + s)*NN + tid] = ss[s];
    }
}

// ---------------- 4b. FFN part 2 + silu + residual (+ bf16 split on last layer) ----------------
__global__ void ffn2_kernel(const float* __restrict__ pc, const float* __restrict__ ps,
                            const float* __restrict__ esc, const float* __restrict__ rsc,
                            int l, int do_split) {
    int m0 = blockIdx.x * 64;
    int n0 = blockIdx.y * 64;
    __shared__ float Ac[64][17], Asm[64][17], Pc[64][17], Ps[64][17];
    int tid = threadIdx.x;
    int ty = tid / 16, tx = tid % 16;
    float accc[4][4] = {}, accs[4][4] = {};
    const float* pcl = pc + l*ND*NN;
    const float* psl = ps + l*ND*NN;
    const float* echob = g_echo + (size_t)l*LAY_X;
    int r  = tid / 4;
    int c4 = (tid % 4) * 4;
    for (int kc = 0; kc < NN; kc += 16) {
        float4 v;
        v = *(const float4*)&g_cs[(m0 + r)*NN + kc + c4];
        Ac[r][c4+0]=v.x; Ac[r][c4+1]=v.y; Ac[r][c4+2]=v.z; Ac[r][c4+3]=v.w;
        v = *(const float4*)&g_ss[(m0 + r)*NN + kc + c4];
        Asm[r][c4+0]=v.x; Asm[r][c4+1]=v.y; Asm[r][c4+2]=v.z; Asm[r][c4+3]=v.w;
        v = *(const float4*)&pcl[(n0 + r)*NN + kc + c4];
        Pc[r][c4+0]=v.x; Pc[r][c4+1]=v.y; Pc[r][c4+2]=v.z; Pc[r][c4+3]=v.w;
        v = *(const float4*)&psl[(n0 + r)*NN + kc + c4];
        Ps[r][c4+0]=v.x; Ps[r][c4+1]=v.y; Ps[r][c4+2]=v.z; Ps[r][c4+3]=v.w;
        __syncthreads();
        #pragma unroll
        for (int kk = 0; kk < 16; kk++) {
            float a1[4], a2[4], b1[4], b2[4];
            #pragma unroll
            for (int i = 0; i < 4; i++) { a1[i] = Ac[ty*4+i][kk]; a2[i] = Asm[ty*4+i][kk]; }
            #pragma unroll
            for (int j = 0; j < 4; j++) { b1[j] = Pc[tx*4+j][kk]; b2[j] = Ps[tx*4+j][kk]; }
            #pragma unroll
            for (int i = 0; i < 4; i++)
                #pragma unroll
                for (int j = 0; j < 4; j++) {
                    accc[i][j] += a1[i]*b1[j];
                    accs[i][j] += a2[i]*b2[j];
                }
        }
        __syncthreads();
    }
    float es = esc[l], rs = rsc[l];
    #pragma unroll
    for (int i = 0; i < 4; i++) {
        int bs = m0 + ty*4 + i;
        #pragma unroll
        for (int j = 0; j < 4; j++) {
            int d = n0 + tx*4 + j;
            float o   = accc[i][j] + accs[i][j];
            float sig = 1.0f / (1.0f + __expf(-o));
            float res = o * sig;
            int xi = bs*ND + d;
            float nx = g_x[xi] + (es * echob[xi] + rs * res);
            g_x[xi] = nx;
            if (do_split) {
                __nv_bfloat16 h = __float2bfloat16(nx);
                g_xh[xi] = h;
                g_xl[xi] = __float2bfloat16(nx - __bfloat162float(h));
            }
        }
    }
}

// ---------------- 5. logits via 3xBF16-split m16n8k16 mma, 128x128 tile ----------------
#define OKC 16
#define OKP (OKC+8)
__global__ __launch_bounds__(256) void out_mma_kernel(float* __restrict__ out) {
    __shared__ __nv_bfloat16 Ah[128][OKP], Al[128][OKP];
    __shared__ __nv_bfloat16 Bh[128][OKP], Bl[128][OKP];
    int tid = threadIdx.x;
    int wid = tid >> 5, lane = tid & 31;
    int wm = wid >> 2, wn = wid & 3;
    int n0 = blockIdx.x * 128;
    int m0 = blockIdx.y * 128;
    int g  = lane >> 2;
    int tg = lane & 3;
    float c[4][4][4];
    #pragma unroll
    for (int a = 0; a < 4; a++)
        #pragma unroll
        for (int bq = 0; bq < 4; bq++)
            #pragma unroll
            for (int k = 0; k < 4; k++) c[a][bq][k] = 0.0f;

    for (int kc = 0; kc < ND; kc += OKC) {
        for (int i = tid; i < 128*8; i += 256) {
            int r = i >> 3, c2 = (i & 7) * 2;
            *(uint32_t*)&Ah[r][c2] = *(const uint32_t*)&g_xh [(m0 + r)*ND + kc + c2];
            *(uint32_t*)&Al[r][c2] = *(const uint32_t*)&g_xl [(m0 + r)*ND + kc + c2];
            *(uint32_t*)&Bh[r][c2] = *(const uint32_t*)&g_oph[(n0 + r)*ND + kc + c2];
            *(uint32_t*)&Bl[r][c2] = *(const uint32_t*)&g_opl[(n0 + r)*ND + kc + c2];
        }
        __syncthreads();
        uint32_t ah[4][4], al[4][4], bh[4][2], bl[4][2];
        #pragma unroll
        for (int mf = 0; mf < 4; mf++) {
            int br = wm*64 + mf*16;
            ah[mf][0] = *(const uint32_t*)&Ah[br + g    ][tg*2    ];
            ah[mf][1] = *(const uint32_t*)&Ah[br + g + 8][tg*2    ];
            ah[mf][2] = *(const uint32_t*)&Ah[br + g    ][tg*2 + 8];
            ah[mf][3] = *(const uint32_t*)&Ah[br + g + 8][tg*2 + 8];
            al[mf][0] = *(const uint32_t*)&Al[br + g    ][tg*2    ];
            al[mf][1] = *(const uint32_t*)&Al[br + g + 8][tg*2    ];
            al[mf][2] = *(const uint32_t*)&Al[br + g    ][tg*2 + 8];
            al[mf][3] = *(const uint32_t*)&Al[br + g + 8][tg*2 + 8];
        }
        #pragma unroll
        for (int nf = 0; nf < 4; nf++) {
            int bc = wn*32 + nf*8 + g;
            bh[nf][0] = *(const uint32_t*)&Bh[bc][tg*2    ];
            bh[nf][1] = *(const uint32_t*)&Bh[bc][tg*2 + 8];
            bl[nf][0] = *(const uint32_t*)&Bl[bc][tg*2    ];
            bl[nf][1] = *(const uint32_t*)&Bl[bc][tg*2 + 8];
        }
        #pragma unroll
        for (int mf = 0; mf < 4; mf++)
            #pragma unroll
            for (int nf = 0; nf < 4; nf++) {
                mma_bf16(c[mf][nf], al[mf], bh[nf]);
                mma_bf16(c[mf][nf], ah[mf], bl[nf]);
                mma_bf16(c[mf][nf], ah[mf], bh[nf]);
            }
        __syncthreads();
    }
    #pragma unroll
    for (int mf = 0; mf < 4; mf++) {
        #pragma unroll
        for (int nf = 0; nf < 4; nf++) {
            int row = m0 + wm*64 + mf*16 + g;
            int col = n0 + wn*32 + nf*8 + 2*tg;
            out[row*NV + col]           = c[mf][nf][0];
            out[row*NV + col + 1]       = c[mf][nf][1];
            out[(row + 8)*NV + col]     = c[mf][nf][2];
            out[(row + 8)*NV + col + 1] = c[mf][nf][3];
        }
    }
}

// ---------------- launch ----------------
extern "C" void kernel_launch(void* const* d_in, const int* in_sizes, int n_in,
                              void* d_out, int out_size) {
    const int*   ids    = (const int*)  d_in[0];
    const float* embed  = (const float*)d_in[1];
    const float* wq     = (const float*)d_in[2];
    const float* bq     = (const float*)d_in[3];
    const float* alpha  = (const float*)d_in[4];
    const float* wout   = (const float*)d_in[5];
    const float* bout   = (const float*)d_in[6];
    const float* ffn_W  = (const float*)d_in[7];
    const float* ffn_B  = (const float*)d_in[8];
    const float* a_cos  = (const float*)d_in[9];
    const float* a_sin  = (const float*)d_in[10];
    const float* p_cos  = (const float*)d_in[11];
    const float* p_sin  = (const float*)d_in[12];
    const float* e_sc   = (const float*)d_in[13];
    const float* r_sc   = (const float*)d_in[14];
    const float* o_proj = (const float*)d_in[15];
    float* out = (float*)d_out;

    gather_kernel<<<(NB*NS*ND + 255)/256, 256>>>(ids, embed);        // 1
    scan_kernel<<<NB, ND>>>();                                        // 2
    ffnprep_kernel<<<(NL*NN*ND + 255)/256, 256>>>(ffn_W, ffn_B, a_cos, a_sin); // 3
    // ffn1(l=0) depends only on scan's g_x + ffnprep — placed 4th so ncu profiles it
    ffn1_kernel<<<NB*NS/SGRP, 256>>>(0);                              // 4 (PROFILED)

    q_kernel<<<(NLH*NB*NS*ND + 255)/256, 256>>>(wq, bq);              // 5
    scores_mma_kernel<<<dim3(NS/64, NS/64, NB*NLH), 256>>>();         // 6
    softmax_kernel<<<dim3(NS/4, NB, NLH), 256>>>();                   // 7
    av_mma_kernel<<<dim3(NS/64, ND2/64, NB*NLH), 256>>>();            // 8
    ema_kernel<<<dim3(NB, NLH), ND>>>(alpha);                         // 9
    echo_kernel<<<(NL*NB*NS*ND + 255)/256, 256>>>(wout, bout);        // 10
    opsplit_kernel<<<(NV*ND/2 + 255)/256, 256>>>(o_proj);             // 11

    ffn2_kernel<<<dim3(NB*NS/64, ND/64), 256>>>(p_cos, p_sin, e_sc, r_sc, 0, 0); // 12
    ffn1_kernel<<<NB*NS/SGRP, 256>>>(1);                              // 13
    ffn2_kernel<<<dim3(NB*NS/64, ND/64), 256>>>(p_cos, p_sin, e_sc, r_sc, 1, 1); // 14

    out_mma_kernel<<<dim3(NV/128, NB*NS/128), 256>>>(out);            // 15
}

// round 17
// speedup vs baseline: 1.3253x; 1.0213x over previous
#include <cuda_runtime.h>
#include <cuda_bf16.h>
#include <math.h>
#include <stdint.h>

#define NB 2
#define NS 1024
#define ND 128
#define ND2 256
#define NN 256
#define NH 2
#define NL 2
#define NLH (NL*NH)
#define NV 32000
#define PHI_F 1.6180339887498949f

#define INST_Q   (NB*NS*ND2)
#define INST_SC  ((size_t)NB*NS*NS)
#define INST_RET (NB*NS*ND2)
#define LAY_X    (NB*NS*ND)

// ---------------- scratch ----------------
static __device__ float g_wemb[NB*NS*ND];
static __device__ float g_bemb[NB*NS*ND];
static __device__ float g_sr  [NB*NS*ND];
static __device__ float g_si  [NB*NS*ND];
static __device__ float g_K   [NB*NS*ND2];
static __device__ float g_x   [NB*NS*ND];
static __device__ float g_Q   [NLH*INST_Q];
static __device__ float g_sc  [NLH*NB*NS*NS];
static __device__ float g_ret [NLH*INST_RET];
static __device__ float g_emah[NLH*LAY_X];
static __device__ float g_echo[NL*LAY_X];
static __device__ float g_cs  [NB*NS*NN];
static __device__ float g_ss  [NB*NS*NN];
static __device__ float g_rwT[NL*ND*NN];
static __device__ float g_bT [NL*ND*NN];
static __device__ float g_acT[NL*ND*NN];
static __device__ float g_asT[NL*ND*NN];
// bf16 hi/lo splits for logits GEMM
static __device__ __nv_bfloat16 g_oph[NV*ND];
static __device__ __nv_bfloat16 g_opl[NV*ND];
static __device__ __nv_bfloat16 g_xh [NB*NS*ND];
static __device__ __nv_bfloat16 g_xl [NB*NS*ND];

__device__ __forceinline__ float to_tf32(float v) {
    float r; asm("cvt.rna.tf32.f32 %0, %1;" : "=f"(r) : "f"(v)); return r;
}
__device__ __forceinline__ void mma_tf32(float* c, const uint32_t* a, const uint32_t* b) {
    asm volatile(
        "mma.sync.aligned.m16n8k8.row.col.f32.tf32.tf32.f32 "
        "{%0,%1,%2,%3},{%4,%5,%6,%7},{%8,%9},{%0,%1,%2,%3};"
        : "+f"(c[0]), "+f"(c[1]), "+f"(c[2]), "+f"(c[3])
        : "r"(a[0]), "r"(a[1]), "r"(a[2]), "r"(a[3]), "r"(b[0]), "r"(b[1]));
}
__device__ __forceinline__ void mma_bf16(float* c, const uint32_t* a, const uint32_t* b) {
    asm volatile(
        "mma.sync.aligned.m16n8k16.row.col.f32.bf16.bf16.f32 "
        "{%0,%1,%2,%3},{%4,%5,%6,%7},{%8,%9},{%0,%1,%2,%3};"
        : "+f"(c[0]), "+f"(c[1]), "+f"(c[2]), "+f"(c[3])
        : "r"(a[0]), "r"(a[1]), "r"(a[2]), "r"(a[3]), "r"(b[0]), "r"(b[1]));
}

// ---------------- 1. gather ----------------
__global__ void gather_kernel(const int* __restrict__ ids, const float* __restrict__ embed) {
    int i = blockIdx.x * blockDim.x + threadIdx.x;
    if (i >= NB*NS*ND) return;
    int d  = i % ND;
    int bs = i / ND;
    int tok = ids[bs];
    g_wemb[i] = embed[tok * ND2 + d];
    g_bemb[i] = embed[tok * ND2 + ND + d];
}

// ---------------- 2. euler scan, register-prefetched — numerics UNCHANGED ----------------
__global__ void scan_kernel() {
    int b = blockIdx.x;
    int d = threadIdx.x;
    float hr = 0.0f, hi = 0.0f;
    int base = b * NS * ND + d;
    float w  = g_wemb[base];
    float bb = g_bemb[base];
    for (int t = 0; t < NS; t++) {
        float wn = 0.0f, bn = 0.0f;
        if (t + 1 < NS) {
            wn = g_wemb[base + (t+1)*ND];
            bn = g_bemb[base + (t+1)*ND];
        }
        float wl = 1.0f + fabsf(w);
        float tphi = (float)t * PHI_F;
        float thr = hr / wl + bb + tphi;
        float thi = hi / wl + bb + tphi;
        float srv, crv, siv, civ;
        sincosf(thr, &srv, &crv);
        sincosf(thi, &siv, &civ);
        float nr = crv * civ - srv * siv;
        float ni = crv * siv + srv * civ;
        g_sr[base + t*ND] = nr;
        g_si[base + t*ND] = ni;
        g_x [base + t*ND] = nr + ni;
        int kb = (b*NS + t) * ND2;
        g_K[kb + d]      = nr;
        g_K[kb + ND + d] = ni;
        hr = nr; hi = ni;
        w = wn; bb = bn;
    }
}

// ---------------- weight prep ----------------
__global__ void ffnprep_kernel(const float* __restrict__ W, const float* __restrict__ Bp,
                               const float* __restrict__ ac, const float* __restrict__ as_) {
    int i = blockIdx.x * blockDim.x + threadIdx.x;
    if (i >= NL*NN*ND) return;
    int l = i / (NN*ND);
    int r = i % (NN*ND);
    int n = r / ND;
    int d = r % ND;
    int o = l*ND*NN + d*NN + n;
    g_rwT[o] = 1.0f / (1.0f + fabsf(W[i]));
    g_bT [o] = Bp[i];
    g_acT[o] = ac[i];
    g_asT[o] = as_[i];
}

// vectorized x2 (element-wise conversion identical)
__global__ void opsplit_kernel(const float* __restrict__ op) {
    int i = (blockIdx.x * blockDim.x + threadIdx.x) * 2;
    if (i >= NV*ND) return;
    float2 v = *(const float2*)&op[i];
    __nv_bfloat16 h0 = __float2bfloat16(v.x);
    __nv_bfloat16 h1 = __float2bfloat16(v.y);
    __nv_bfloat16 l0 = __float2bfloat16(v.x - __bfloat162float(h0));
    __nv_bfloat16 l1 = __float2bfloat16(v.y - __bfloat162float(h1));
    __nv_bfloat162 hp; hp.x = h0; hp.y = h1;
    __nv_bfloat162 lp; lp.x = l0; lp.y = l1;
    *(__nv_bfloat162*)&g_oph[i] = hp;
    *(__nv_bfloat162*)&g_opl[i] = lp;
}

// ---------------- 3a. Q (MUFU cos; 1/16 scale folded in — exact pow2) ----------------
__global__ void q_kernel(const float* __restrict__ wq, const float* __restrict__ bq) {
    int i = blockIdx.x * blockDim.x + threadIdx.x;
    if (i >= NLH*NB*NS*ND) return;
    int inst = i / (NB*NS*ND);
    int j  = i % (NB*NS*ND);
    int d  = j % ND;
    int bs = j / ND;
    int t  = bs % NS;
    float wlq = 1.0f + fabsf(wq[inst*ND + d]);
    float bqv = bq[inst*ND + d];
    float tphi = (float)t * PHI_F;
    float thr = g_sr[j] / wlq + bqv + tphi;
    float thi = g_si[j] / wlq + bqv + tphi;
    float* Qb = g_Q + (size_t)inst*INST_Q;
    Qb[bs*ND2 + d]      = __cosf(thr) * 0.0625f;
    Qb[bs*ND2 + ND + d] = __cosf(thi) * 0.0625f;
}

// ---------------- 3b. scores via TF32 mma ----------------
#define KC 16
__global__ __launch_bounds__(256) void scores_mma_kernel() {
    int z = blockIdx.z;
    int b    = z % NB;
    int inst = z / NB;
    int q0 = blockIdx.x * 64;
    int k0 = blockIdx.y * 64;
    if (k0 > q0 + 63) return;
    const float* Qb = g_Q + (size_t)inst*INST_Q;
    float* scb = g_sc + (size_t)inst*INST_SC;
    __shared__ float Qs[64][KC+5];
    __shared__ float Ks[64][KC+5];
    int tid = threadIdx.x;
    int wid = tid >> 5, lane = tid & 31;
    int wm = wid >> 2, wn = wid & 3;
    int g  = lane >> 2, tg = lane & 3;
    float c[2][2][4];
    #pragma unroll
    for (int i = 0; i < 2; i++)
        #pragma unroll
        for (int j = 0; j < 2; j++)
            #pragma unroll
            for (int k = 0; k < 4; k++) c[i][j][k] = 0.0f;

    for (int kc = 0; kc < ND2; kc += KC) {
        for (int i = tid; i < 64*KC; i += 256) {
            int r = i >> 4, cc = i & 15;
            Qs[r][cc] = to_tf32(Qb[(b*NS + q0 + r)*ND2 + kc + cc]);
            Ks[r][cc] = to_tf32(g_K[(b*NS + k0 + r)*ND2 + kc + cc]);
        }
        __syncthreads();
        #pragma unroll
        for (int ks = 0; ks < KC; ks += 8) {
            uint32_t a[2][4], bf[2][2];
            #pragma unroll
            for (int mf = 0; mf < 2; mf++) {
                int br = wm*32 + mf*16;
                a[mf][0] = __float_as_uint(Qs[br + g    ][ks + tg    ]);
                a[mf][1] = __float_as_uint(Qs[br + g + 8][ks + tg    ]);
                a[mf][2] = __float_as_uint(Qs[br + g    ][ks + tg + 4]);
                a[mf][3] = __float_as_uint(Qs[br + g + 8][ks + tg + 4]);
            }
            #pragma unroll
            for (int nf = 0; nf < 2; nf++) {
                int bc = wn*16 + nf*8 + g;
                bf[nf][0] = __float_as_uint(Ks[bc][ks + tg    ]);
                bf[nf][1] = __float_as_uint(Ks[bc][ks + tg + 4]);
            }
            #pragma unroll
            for (int mf = 0; mf < 2; mf++)
                #pragma unroll
                for (int nf = 0; nf < 2; nf++)
                    mma_tf32(c[mf][nf], a[mf], bf[nf]);
        }
        __syncthreads();
    }
    #pragma unroll
    for (int mf = 0; mf < 2; mf++) {
        #pragma unroll
        for (int nf = 0; nf < 2; nf++) {
            int row = q0 + wm*32 + mf*16 + g;
            int col = k0 + wn*16 + nf*8 + 2*tg;
            size_t base0 = (size_t)(b*NS + row)*NS;
            size_t base1 = (size_t)(b*NS + row + 8)*NS;
            if (col     <= row)   scb[base0 + col]     = c[mf][nf][0];
            if (col + 1 <= row)   scb[base0 + col + 1] = c[mf][nf][1];
            if (col     <= row+8) scb[base1 + col]     = c[mf][nf][2];
            if (col + 1 <= row+8) scb[base1 + col + 1] = c[mf][nf][3];
        }
    }
}

// ---------------- 3c. softmax: 4 rows/block, 64 threads/row, shfl reductions ----------------
__global__ void softmax_kernel() {
    int tid = threadIdx.x;
    int gr = tid >> 6, lt = tid & 63;
    int q = blockIdx.x * 4 + gr;
    int b = blockIdx.y;
    int inst = blockIdx.z;
    float* row = g_sc + (size_t)inst*INST_SC + (size_t)(b*NS + q)*NS;
    __shared__ float wsum[8];
    bool isq0 = (q == 0);
    int len = q + 1;
    int kz_end = (q & ~63) + 64;
    float v[16];
    float sum = 0.0f;
    if (!isq0) {
        #pragma unroll
        for (int j = 0; j < 16; j++) {
            int k = lt + j*64;
            if (k < len) { v[j] = __expf(row[k]); sum += v[j]; }
            else v[j] = 0.0f;
        }
    }
    #pragma unroll
    for (int o = 16; o > 0; o >>= 1) sum += __shfl_xor_sync(0xffffffffu, sum, o);
    if ((tid & 31) == 0) wsum[tid >> 5] = sum;
    __syncthreads();
    if (isq0) {
        row[lt] = (lt == 0) ? 1.0f : 0.0f;
    } else {
        float inv = 1.0f / (wsum[gr*2] + wsum[gr*2 + 1]);
        #pragma unroll
        for (int j = 0; j < 16; j++) {
            int k = lt + j*64;
            if (k < len)         row[k] = v[j] * inv;
            else if (k < kz_end) row[k] = 0.0f;
        }
    }
}

// ---------------- 3d. retrieved = attn @ K via TF32 mma ----------------
__global__ __launch_bounds__(256) void av_mma_kernel() {
    int z = blockIdx.z;
    int b    = z % NB;
    int inst = z / NB;
    int q0 = blockIdx.x * 64;
    int n0 = blockIdx.y * 64;
    const float* scb = g_sc + (size_t)inst*INST_SC;
    float* retb = g_ret + (size_t)inst*INST_RET;
    __shared__ float As[64][KC+5];
    __shared__ float Bs[64][KC+5];
    int tid = threadIdx.x;
    int wid = tid >> 5, lane = tid & 31;
    int wm = wid >> 2, wn = wid & 3;
    int g  = lane >> 2, tg = lane & 3;
    float c[2][2][4];
    #pragma unroll
    for (int i = 0; i < 2; i++)
        #pragma unroll
        for (int j = 0; j < 2; j++)
            #pragma unroll
            for (int k = 0; k < 4; k++) c[i][j][k] = 0.0f;

    int kend = q0 + 64;
    for (int kc = 0; kc < kend; kc += KC) {
        for (int i = tid; i < 64*KC; i += 256) {
            int r = i >> 4, cc = i & 15;
            As[r][cc] = to_tf32(scb[(size_t)(b*NS + q0 + r)*NS + kc + cc]);
        }
        for (int i = tid; i < KC*64; i += 256) {
            int kk = i >> 6, n = i & 63;
            Bs[n][kk] = to_tf32(g_K[(b*NS + kc + kk)*ND2 + n0 + n]);
        }
        __syncthreads();
        #pragma unroll
        for (int ks = 0; ks < KC; ks += 8) {
            uint32_t a[2][4], bf[2][2];
            #pragma unroll
            for (int mf = 0; mf < 2; mf++) {
                int br = wm*32 + mf*16;
                a[mf][0] = __float_as_uint(As[br + g    ][ks + tg    ]);
                a[mf][1] = __float_as_uint(As[br + g + 8][ks + tg    ]);
                a[mf][2] = __float_as_uint(As[br + g    ][ks + tg + 4]);
                a[mf][3] = __float_as_uint(As[br + g + 8][ks + tg + 4]);
            }
            #pragma unroll
            for (int nf = 0; nf < 2; nf++) {
                int bc = wn*16 + nf*8 + g;
                bf[nf][0] = __float_as_uint(Bs[bc][ks + tg    ]);
                bf[nf][1] = __float_as_uint(Bs[bc][ks + tg + 4]);
            }
            #pragma unroll
            for (int mf = 0; mf < 2; mf++)
                #pragma unroll
                for (int nf = 0; nf < 2; nf++)
                    mma_tf32(c[mf][nf], a[mf], bf[nf]);
        }
        __syncthreads();
    }
    #pragma unroll
    for (int mf = 0; mf < 2; mf++) {
        #pragma unroll
        for (int nf = 0; nf < 2; nf++) {
            int row = q0 + wm*32 + mf*16 + g;
            int col = n0 + wn*16 + nf*8 + 2*tg;
            retb[(b*NS + row)*ND2 + col]       = c[mf][nf][0];
            retb[(b*NS + row)*ND2 + col + 1]   = c[mf][nf][1];
            retb[(b*NS + row + 8)*ND2 + col]     = c[mf][nf][2];
            retb[(b*NS + row + 8)*ND2 + col + 1] = c[mf][nf][3];
        }
    }
}

// ---------------- 3e. EMA — unroll-4 + register prefetch (bit-identical FMA order) ----------------
__global__ void ema_kernel(const float* __restrict__ alpha) {
    int b = blockIdx.x;
    int inst = blockIdx.y;
    int d = threadIdx.x;
    const float* retb = g_ret + (size_t)inst*INST_RET;
    float* eb = g_emah + (size_t)inst*LAY_X;
    float ap = alpha[inst];
    float a  = 1.0f / (1.0f + expf(-ap));
    float om = 1.0f - a;
    float e1 = 0.0f, e2 = 0.0f;
    for (int t0 = 0; t0 < NS; t0 += 4) {
        float r1v[4], r2v[4];
        #pragma unroll
        for (int j = 0; j < 4; j++) {
            int idx = (b*NS + t0 + j) * ND2;
            r1v[j] = retb[idx + d];
            r2v[j] = retb[idx + ND + d];
        }
        #pragma unroll
        for (int j = 0; j < 4; j++) {
            e1 = a * r1v[j] + om * e1;
            e2 = a * r2v[j] + om * e2;
            eb[(b*NS + t0 + j)*ND + d] = e1 + e2;
        }
    }
}

// ---------------- 3f. echo ----------------
__global__ void echo_kernel(const float* __restrict__ wout, const float* __restrict__ bout) {
    int i = blockIdx.x * blockDim.x + threadIdx.x;
    if (i >= NL*NB*NS*ND) return;
    int l = i / LAY_X;
    int j = i % LAY_X;
    int d = j % ND;
    float comb = g_emah[(size_t)(l*NH + 0)*LAY_X + j] + g_emah[(size_t)(l*NH + 1)*LAY_X + j];
    float wl = 1.0f + fabsf(wout[l*ND + d]);
    float th = comb / wl + bout[l*ND + d];
    float sv, cv; __sincosf(th, &sv, &cv);
    g_echo[(size_t)l*LAY_X + j] = cv + sv;
}

// ---------------- 4a. FFN part 1 — 512 threads (2 s-groups), bit-identical per-output order ----------------
#define SGRP 8
#define FFN1_THR 512
__global__ __launch_bounds__(FFN1_THR) void ffn1_kernel(int l) {
    int blk = blockIdx.x;
    int b  = blk / (NS/SGRP);
    int s0 = (blk % (NS/SGRP)) * SGRP;
    __shared__ float xs[SGRP][ND];
    int tid = threadIdx.x;
    for (int i = tid; i < SGRP*ND; i += FFN1_THR)
        xs[i/ND][i%ND] = g_x[(b*NS + s0 + i/ND)*ND + (i%ND)];
    __syncthreads();
    int sg = tid >> 8;            // 0 or 1 — owns rows sg*4 .. sg*4+3
    int n  = tid & 255;
    const float* rwT = g_rwT + l*ND*NN;
    const float* bT  = g_bT  + l*ND*NN;
    const float* acT = g_acT + l*ND*NN;
    const float* asT = g_asT + l*ND*NN;
    float sc[4] = {}, ss[4] = {};
    for (int d = 0; d < ND; d++) {
        float rw = rwT[d*NN + n];
        float bb = bT [d*NN + n];
        float ac = acT[d*NN + n];
        float as = asT[d*NN + n];
        #pragma unroll
        for (int s = 0; s < 4; s++) {
            float th = xs[sg*4 + s][d] * rw + bb;
            float sv, cv; __sincosf(th, &sv, &cv);
            sc[s] += cv * ac;
            ss[s] += sv * as;
        }
    }
    #pragma unroll
    for (int s = 0; s < 4; s++) {
        g_cs[(b*NS + s0 + sg*4 + s)*NN + n] = sc[s];
        g_ss[(b*NS + s0 + sg*4 + s)*NN + n] = ss[s];
    }
}

// ---------------- 4b. FFN part 2 + silu + residual (+ bf16 split on last layer) ----------------
__global__ void ffn2_kernel(const float* __restrict__ pc, const float* __restrict__ ps,
                            const float* __restrict__ esc, const float* __restrict__ rsc,
                            int l, int do_split) {
    int m0 = blockIdx.x * 64;
    int n0 = blockIdx.y * 64;
    __shared__ float Ac[64][17], Asm[64][17], Pc[64][17], Ps[64][17];
    int tid = threadIdx.x;
    int ty = tid / 16, tx = tid % 16;
    float accc[4][4] = {}, accs[4][4] = {};
    const float* pcl = pc + l*ND*NN;
    const float* psl = ps + l*ND*NN;
    const float* echob = g_echo + (size_t)l*LAY_X;
    int r  = tid / 4;
    int c4 = (tid % 4) * 4;
    for (int kc = 0; kc < NN; kc += 16) {
        float4 v;
        v = *(const float4*)&g_cs[(m0 + r)*NN + kc + c4];
        Ac[r][c4+0]=v.x; Ac[r][c4+1]=v.y; Ac[r][c4+2]=v.z; Ac[r][c4+3]=v.w;
        v = *(const float4*)&g_ss[(m0 + r)*NN + kc + c4];
        Asm[r][c4+0]=v.x; Asm[r][c4+1]=v.y; Asm[r][c4+2]=v.z; Asm[r][c4+3]=v.w;
        v = *(const float4*)&pcl[(n0 + r)*NN + kc + c4];
        Pc[r][c4+0]=v.x; Pc[r][c4+1]=v.y; Pc[r][c4+2]=v.z; Pc[r][c4+3]=v.w;
        v = *(const float4*)&psl[(n0 + r)*NN + kc + c4];
        Ps[r][c4+0]=v.x; Ps[r][c4+1]=v.y; Ps[r][c4+2]=v.z; Ps[r][c4+3]=v.w;
        __syncthreads();
        #pragma unroll
        for (int kk = 0; kk < 16; kk++) {
            float a1[4], a2[4], b1[4], b2[4];
            #pragma unroll
            for (int i = 0; i < 4; i++) { a1[i] = Ac[ty*4+i][kk]; a2[i] = Asm[ty*4+i][kk]; }
            #pragma unroll
            for (int j = 0; j < 4; j++) { b1[j] = Pc[tx*4+j][kk]; b2[j] = Ps[tx*4+j][kk]; }
            #pragma unroll
            for (int i = 0; i < 4; i++)
                #pragma unroll
                for (int j = 0; j < 4; j++) {
                    accc[i][j] += a1[i]*b1[j];
                    accs[i][j] += a2[i]*b2[j];
                }
        }
        __syncthreads();
    }
    float es = esc[l], rs = rsc[l];
    #pragma unroll
    for (int i = 0; i < 4; i++) {
        int bs = m0 + ty*4 + i;
        #pragma unroll
        for (int j = 0; j < 4; j++) {
            int d = n0 + tx*4 + j;
            float o   = accc[i][j] + accs[i][j];
            float sig = 1.0f / (1.0f + __expf(-o));
            float res = o * sig;
            int xi = bs*ND + d;
            float nx = g_x[xi] + (es * echob[xi] + rs * res);
            g_x[xi] = nx;
            if (do_split) {
                __nv_bfloat16 h = __float2bfloat16(nx);
                g_xh[xi] = h;
                g_xl[xi] = __float2bfloat16(nx - __bfloat162float(h));
            }
        }
    }
}

// ---------------- 5. logits via 3xBF16-split m16n8k16 mma, 128x128 tile ----------------
#define OKC 16
#define OKP (OKC+8)
__global__ __launch_bounds__(256) void out_mma_kernel(float* __restrict__ out) {
    __shared__ __nv_bfloat16 Ah[128][OKP], Al[128][OKP];
    __shared__ __nv_bfloat16 Bh[128][OKP], Bl[128][OKP];
    int tid = threadIdx.x;
    int wid = tid >> 5, lane = tid & 31;
    int wm = wid >> 2, wn = wid & 3;
    int n0 = blockIdx.x * 128;
    int m0 = blockIdx.y * 128;
    int g  = lane >> 2;
    int tg = lane & 3;
    float c[4][4][4];
    #pragma unroll
    for (int a = 0; a < 4; a++)
        #pragma unroll
        for (int bq = 0; bq < 4; bq++)
            #pragma unroll
            for (int k = 0; k < 4; k++) c[a][bq][k] = 0.0f;

    for (int kc = 0; kc < ND; kc += OKC) {
        for (int i = tid; i < 128*8; i += 256) {
            int r = i >> 3, c2 = (i & 7) * 2;
            *(uint32_t*)&Ah[r][c2] = *(const uint32_t*)&g_xh [(m0 + r)*ND + kc + c2];
            *(uint32_t*)&Al[r][c2] = *(const uint32_t*)&g_xl [(m0 + r)*ND + kc + c2];
            *(uint32_t*)&Bh[r][c2] = *(const uint32_t*)&g_oph[(n0 + r)*ND + kc + c2];
            *(uint32_t*)&Bl[r][c2] = *(const uint32_t*)&g_opl[(n0 + r)*ND + kc + c2];
        }
        __syncthreads();
        uint32_t ah[4][4], al[4][4], bh[4][2], bl[4][2];
        #pragma unroll
        for (int mf = 0; mf < 4; mf++) {
            int br = wm*64 + mf*16;
            ah[mf][0] = *(const uint32_t*)&Ah[br + g    ][tg*2    ];
            ah[mf][1] = *(const uint32_t*)&Ah[br + g + 8][tg*2    ];
            ah[mf][2] = *(const uint32_t*)&Ah[br + g    ][tg*2 + 8];
            ah[mf][3] = *(const uint32_t*)&Ah[br + g + 8][tg*2 + 8];
            al[mf][0] = *(const uint32_t*)&Al[br + g    ][tg*2    ];
            al[mf][1] = *(const uint32_t*)&Al[br + g + 8][tg*2    ];
            al[mf][2] = *(const uint32_t*)&Al[br + g    ][tg*2 + 8];
            al[mf][3] = *(const uint32_t*)&Al[br + g + 8][tg*2 + 8];
        }
        #pragma unroll
        for (int nf = 0; nf < 4; nf++) {
            int bc = wn*32 + nf*8 + g;
            bh[nf][0] = *(const uint32_t*)&Bh[bc][tg*2    ];
            bh[nf][1] = *(const uint32_t*)&Bh[bc][tg*2 + 8];
            bl[nf][0] = *(const uint32_t*)&Bl[bc][tg*2    ];
            bl[nf][1] = *(const uint32_t*)&Bl[bc][tg*2 + 8];
        }
        #pragma unroll
        for (int mf = 0; mf < 4; mf++)
            #pragma unroll
            for (int nf = 0; nf < 4; nf++) {
                mma_bf16(c[mf][nf], al[mf], bh[nf]);
                mma_bf16(c[mf][nf], ah[mf], bl[nf]);
                mma_bf16(c[mf][nf], ah[mf], bh[nf]);
            }
        __syncthreads();
    }
    #pragma unroll
    for (int mf = 0; mf < 4; mf++) {
        #pragma unroll
        for (int nf = 0; nf < 4; nf++) {
            int row = m0 + wm*64 + mf*16 + g;
            int col = n0 + wn*32 + nf*8 + 2*tg;
            out[row*NV + col]           = c[mf][nf][0];
            out[row*NV + col + 1]       = c[mf][nf][1];
            out[(row + 8)*NV + col]     = c[mf][nf][2];
            out[(row + 8)*NV + col + 1] = c[mf][nf][3];
        }
    }
}

// ---------------- launch ----------------
extern "C" void kernel_launch(void* const* d_in, const int* in_sizes, int n_in,
                              void* d_out, int out_size) {
    const int*   ids    = (const int*)  d_in[0];
    const float* embed  = (const float*)d_in[1];
    const float* wq     = (const float*)d_in[2];
    const float* bq     = (const float*)d_in[3];
    const float* alpha  = (const float*)d_in[4];
    const float* wout   = (const float*)d_in[5];
    const float* bout   = (const float*)d_in[6];
    const float* ffn_W  = (const float*)d_in[7];
    const float* ffn_B  = (const float*)d_in[8];
    const float* a_cos  = (const float*)d_in[9];
    const float* a_sin  = (const float*)d_in[10];
    const float* p_cos  = (const float*)d_in[11];
    const float* p_sin  = (const float*)d_in[12];
    const float* e_sc   = (const float*)d_in[13];
    const float* r_sc   = (const float*)d_in[14];
    const float* o_proj = (const float*)d_in[15];
    float* out = (float*)d_out;

    gather_kernel<<<(NB*NS*ND + 255)/256, 256>>>(ids, embed);        // 1
    ffnprep_kernel<<<(NL*NN*ND + 255)/256, 256>>>(ffn_W, ffn_B, a_cos, a_sin); // 2
    opsplit_kernel<<<(NV*ND/2 + 255)/256, 256>>>(o_proj);             // 3
    scan_kernel<<<NB, ND>>>();                                        // 4 (PROFILED)

    ffn1_kernel<<<NB*NS/SGRP, FFN1_THR>>>(0);                         // 5
    q_kernel<<<(NLH*NB*NS*ND + 255)/256, 256>>>(wq, bq);              // 6
    scores_mma_kernel<<<dim3(NS/64, NS/64, NB*NLH), 256>>>();         // 7
    softmax_kernel<<<dim3(NS/4, NB, NLH), 256>>>();                   // 8
    av_mma_kernel<<<dim3(NS/64, ND2/64, NB*NLH), 256>>>();            // 9
    ema_kernel<<<dim3(NB, NLH), ND>>>(alpha);                         // 10
    echo_kernel<<<(NL*NB*NS*ND + 255)/256, 256>>>(wout, bout);        // 11

    ffn2_kernel<<<dim3(NB*NS/64, ND/64), 256>>>(p_cos, p_sin, e_sc, r_sc, 0, 0); // 12
    ffn1_kernel<<<NB*NS/SGRP, FFN1_THR>>>(1);                         // 13
    ffn2_kernel<<<dim3(NB*NS/64, ND/64), 256>>>(p_cos, p_sin, e_sc, r_sc, 1, 1); // 14

    out_mma_kernel<<<dim3(NV/128, NB*NS/128), 256>>>(out);            // 15
}